// round 3
// baseline (speedup 1.0000x reference)
#include <cuda_runtime.h>

// Problem constants
#define S_LEN 1024
#define BATCH 2
#define DM    768
#define NH    12
#define HD    64
#define NTILE 16          // S_LEN / 64 query tiles

// Scratch (device globals — no allocation allowed)
__device__ float g_q[BATCH * S_LEN * DM];
__device__ float g_k[BATCH * S_LEN * DM];
__device__ float g_v[BATCH * S_LEN * DM];
__device__ float g_part[BATCH * NTILE * DM];   // per-tile pooled partial sums

// Packed fp32x2 FMA (FFMA2) — ptxas never auto-fuses this from C++.
__device__ __forceinline__ void ffma2(unsigned long long& acc,
                                      unsigned long long a,
                                      unsigned long long b) {
    asm("fma.rn.f32x2 %0, %1, %2, %0;" : "+l"(acc) : "l"(a), "l"(b));
}
__device__ __forceinline__ unsigned long long bcast2(float a) {
    unsigned long long r;
    asm("mov.b64 %0, {%1, %1};" : "=l"(r) : "f"(a));
    return r;
}

// ---------------------------------------------------------------------------
// QKV GEMM: C = A(2048x768) @ W(768x768) + bias, blockIdx.z selects Q/K/V.
// 128x128 tile, BK=16, 256 threads, 8x8 per thread.
// Double-buffered smem + packed fma.rn.f32x2 accumulation.
// ---------------------------------------------------------------------------
__global__ __launch_bounds__(256, 2) void qkv_gemm(
    const float* __restrict__ A,
    const float* __restrict__ Wq, const float* __restrict__ bq,
    const float* __restrict__ Wk, const float* __restrict__ bk,
    const float* __restrict__ Wv, const float* __restrict__ bv)
{
    const float* W; const float* bias; float* C;
    if (blockIdx.z == 0)      { W = Wq; bias = bq; C = g_q; }
    else if (blockIdx.z == 1) { W = Wk; bias = bk; C = g_k; }
    else                      { W = Wv; bias = bv; C = g_v; }

    __shared__ float As[2][16 * 132];   // [k][m], padded stride 132
    __shared__ float Bs[2][16 * 128];   // [k][n]

    const int tid = threadIdx.x;
    const int tx  = tid & 15;        // n-group (8 cols each)
    const int ty  = tid >> 4;        // m-group (8 rows each)
    const int m0  = blockIdx.y * 128;
    const int n0  = blockIdx.x * 128;

    const int aRow = tid >> 1;            // 0..127
    const int aC   = (tid & 1) * 8;       // 0 or 8
    const int bRow = tid >> 4;            // 0..15
    const int bC   = (tid & 15) * 8;      // 0..120

    const float* Aptr = A + (m0 + aRow) * DM + aC;
    const float* Wptr = W + bRow * DM + n0 + bC;

    // Packed accumulators: accP[i][j2] holds columns (2*j2, 2*j2+1) of row i
    unsigned long long accP[8][4];
    #pragma unroll
    for (int i = 0; i < 8; i++)
        #pragma unroll
        for (int j = 0; j < 4; j++) accP[i][j] = 0ull;

    // Prologue: load tile 0 and stage into buffer 0
    {
        float4 aP0 = *(const float4*)(Aptr + 0);
        float4 aP1 = *(const float4*)(Aptr + 4);
        float4 bP0 = *(const float4*)(Wptr + 0);
        float4 bP1 = *(const float4*)(Wptr + 4);
        As[0][(aC + 0) * 132 + aRow] = aP0.x;
        As[0][(aC + 1) * 132 + aRow] = aP0.y;
        As[0][(aC + 2) * 132 + aRow] = aP0.z;
        As[0][(aC + 3) * 132 + aRow] = aP0.w;
        As[0][(aC + 4) * 132 + aRow] = aP1.x;
        As[0][(aC + 5) * 132 + aRow] = aP1.y;
        As[0][(aC + 6) * 132 + aRow] = aP1.z;
        As[0][(aC + 7) * 132 + aRow] = aP1.w;
        *(float4*)&Bs[0][bRow * 128 + bC + 0] = bP0;
        *(float4*)&Bs[0][bRow * 128 + bC + 4] = bP1;
    }
    __syncthreads();

    int buf = 0;
    for (int k0 = 0; k0 < DM; k0 += 16) {
        const bool has_next = (k0 + 16) < DM;
        float4 aP0, aP1, bP0, bP1;
        if (has_next) {
            Aptr += 16;
            Wptr += 16 * DM;
            aP0 = *(const float4*)(Aptr + 0);
            aP1 = *(const float4*)(Aptr + 4);
            bP0 = *(const float4*)(Wptr + 0);
            bP1 = *(const float4*)(Wptr + 4);
        }

        const float* Asb = As[buf];
        const float* Bsb = Bs[buf];
        #pragma unroll
        for (int kk = 0; kk < 16; kk++) {
            float4 a0 = *(const float4*)&Asb[kk * 132 + ty * 8 + 0];
            float4 a1 = *(const float4*)&Asb[kk * 132 + ty * 8 + 4];
            // b row as 4 packed f32x2 (64-bit loads, pairs in lane order)
            const unsigned long long* bp =
                (const unsigned long long*)&Bsb[kk * 128 + tx * 8];
            unsigned long long b0 = bp[0], b1 = bp[1], b2 = bp[2], b3 = bp[3];
            float ar[8] = {a0.x, a0.y, a0.z, a0.w, a1.x, a1.y, a1.z, a1.w};
            #pragma unroll
            for (int i = 0; i < 8; i++) {
                unsigned long long aa = bcast2(ar[i]);
                ffma2(accP[i][0], aa, b0);
                ffma2(accP[i][1], aa, b1);
                ffma2(accP[i][2], aa, b2);
                ffma2(accP[i][3], aa, b3);
            }
        }

        if (has_next) {
            const int nb = buf ^ 1;
            As[nb][(aC + 0) * 132 + aRow] = aP0.x;
            As[nb][(aC + 1) * 132 + aRow] = aP0.y;
            As[nb][(aC + 2) * 132 + aRow] = aP0.z;
            As[nb][(aC + 3) * 132 + aRow] = aP0.w;
            As[nb][(aC + 4) * 132 + aRow] = aP1.x;
            As[nb][(aC + 5) * 132 + aRow] = aP1.y;
            As[nb][(aC + 6) * 132 + aRow] = aP1.z;
            As[nb][(aC + 7) * 132 + aRow] = aP1.w;
            *(float4*)&Bs[nb][bRow * 128 + bC + 0] = bP0;
            *(float4*)&Bs[nb][bRow * 128 + bC + 4] = bP1;
            __syncthreads();
            buf = nb;
        }
    }

    float4 bias0 = *(const float4*)&bias[n0 + tx * 8 + 0];
    float4 bias1 = *(const float4*)&bias[n0 + tx * 8 + 4];
    const float bb[8] = {bias0.x, bias0.y, bias0.z, bias0.w,
                         bias1.x, bias1.y, bias1.z, bias1.w};
    #pragma unroll
    for (int i = 0; i < 8; i++) {
        int m = m0 + ty * 8 + i;
        float c[8];
        #pragma unroll
        for (int j = 0; j < 4; j++) {
            float2 v = *(float2*)&accP[i][j];
            c[2 * j + 0] = v.x + bb[2 * j + 0];
            c[2 * j + 1] = v.y + bb[2 * j + 1];
        }
        *(float4*)&C[m * DM + n0 + tx * 8 + 0] = make_float4(c[0], c[1], c[2], c[3]);
        *(float4*)&C[m * DM + n0 + tx * 8 + 4] = make_float4(c[4], c[5], c[6], c[7]);
    }
}

// ---------------------------------------------------------------------------
// Windowed attention per (tile of 64 queries, head, batch) + per-tile pooling.
// smem: q(64x68) | k(128x68) | v(128x68) | attn(64x68)  = 104448 B dynamic
// ---------------------------------------------------------------------------
__global__ __launch_bounds__(256) void attn_kernel()
{
    const int tile = blockIdx.x;   // 0..15
    const int h    = blockIdx.y;   // 0..11
    const int b    = blockIdx.z;   // 0..1
    const int s0   = tile * 64;
    const int colbase = h * HD;

    extern __shared__ float sm[];
    float* q_sm = sm;                    // 64*68
    float* k_sm = q_sm + 64 * 68;        // 128*68
    float* v_sm = k_sm + 128 * 68;       // 128*68
    float* a_sm = v_sm + 128 * 68;       // 64*68 (scores/attn, then reduce buf)

    const int tid = threadIdx.x;

    // Load Q tile (64 rows x 64 dims)
    for (int i = tid; i < 64 * 16; i += 256) {
        int row = i >> 4;
        int c4  = (i & 15) << 2;
        float4 v = *(const float4*)&g_q[((b * S_LEN) + s0 + row) * DM + colbase + c4];
        *(float4*)&q_sm[row * 68 + c4] = v;
    }
    // Load K/V window (rows s0-32 .. s0+95), zero-fill out of range
    for (int i = tid; i < 128 * 16; i += 256) {
        int row  = i >> 4;
        int c4   = (i & 15) << 2;
        int srow = s0 - 32 + row;
        float4 kv = make_float4(0.f, 0.f, 0.f, 0.f);
        float4 vv = make_float4(0.f, 0.f, 0.f, 0.f);
        if (srow >= 0 && srow < S_LEN) {
            kv = *(const float4*)&g_k[((b * S_LEN) + srow) * DM + colbase + c4];
            vv = *(const float4*)&g_v[((b * S_LEN) + srow) * DM + colbase + c4];
        }
        *(float4*)&k_sm[row * 68 + c4] = kv;
        *(float4*)&v_sm[row * 68 + c4] = vv;
    }
    __syncthreads();

    const int qi  = tid >> 2;       // query within tile
    const int sub = tid & 3;        // sub-lane within query group
    const int sglob = s0 + qi;

    // ---- scores for window positions w = sub, sub+4, ... (<=64) ----
    float sc[17];
    const int nw = (sub == 0) ? 17 : 16;
    const float* qr = &q_sm[qi * 68];
    for (int j = 0; j < nw; j++) {
        int w = sub + 4 * j;
        const float* kr = &k_sm[(qi + w) * 68];
        float s = 0.f;
        #pragma unroll
        for (int dc = 0; dc < 16; dc++) {
            float4 qv = *(const float4*)&qr[dc * 4];
            float4 kv = *(const float4*)&kr[dc * 4];
            s = fmaf(qv.x, kv.x, s);
            s = fmaf(qv.y, kv.y, s);
            s = fmaf(qv.z, kv.z, s);
            s = fmaf(qv.w, kv.w, s);
        }
        int ks = sglob - 32 + w;
        sc[j] = (ks >= 0 && ks < S_LEN) ? s * 0.125f : -1e9f;
    }

    // ---- softmax across the 4-lane group ----
    float m = -1e30f;
    for (int j = 0; j < nw; j++) m = fmaxf(m, sc[j]);
    m = fmaxf(m, __shfl_xor_sync(0xffffffffu, m, 1));
    m = fmaxf(m, __shfl_xor_sync(0xffffffffu, m, 2));
    float lsum = 0.f;
    for (int j = 0; j < nw; j++) { sc[j] = __expf(sc[j] - m); lsum += sc[j]; }
    lsum += __shfl_xor_sync(0xffffffffu, lsum, 1);
    lsum += __shfl_xor_sync(0xffffffffu, lsum, 2);
    float rinv = 1.0f / lsum;
    for (int j = 0; j < nw; j++)
        a_sm[qi * 68 + sub + 4 * j] = sc[j] * rinv;
    __syncthreads();

    // ---- out[qi][d0..d0+15] = sum_w attn * v ----
    const int d0 = sub * 16;
    float4 acc0 = make_float4(0.f, 0.f, 0.f, 0.f);
    float4 acc1 = acc0, acc2 = acc0, acc3 = acc0;
    const float* ar = &a_sm[qi * 68];
    for (int w = 0; w < 65; w++) {
        float p = ar[w];
        const float* vr = &v_sm[(qi + w) * 68 + d0];
        float4 v0 = *(const float4*)&vr[0];
        float4 v1 = *(const float4*)&vr[4];
        float4 v2 = *(const float4*)&vr[8];
        float4 v3 = *(const float4*)&vr[12];
        acc0.x = fmaf(p, v0.x, acc0.x); acc0.y = fmaf(p, v0.y, acc0.y);
        acc0.z = fmaf(p, v0.z, acc0.z); acc0.w = fmaf(p, v0.w, acc0.w);
        acc1.x = fmaf(p, v1.x, acc1.x); acc1.y = fmaf(p, v1.y, acc1.y);
        acc1.z = fmaf(p, v1.z, acc1.z); acc1.w = fmaf(p, v1.w, acc1.w);
        acc2.x = fmaf(p, v2.x, acc2.x); acc2.y = fmaf(p, v2.y, acc2.y);
        acc2.z = fmaf(p, v2.z, acc2.z); acc2.w = fmaf(p, v2.w, acc2.w);
        acc3.x = fmaf(p, v3.x, acc3.x); acc3.y = fmaf(p, v3.y, acc3.y);
        acc3.z = fmaf(p, v3.z, acc3.z); acc3.w = fmaf(p, v3.w, acc3.w);
    }

    // Store per-query outputs into q_sm (safe: q_sm reads ended before prior barrier)
    *(float4*)&q_sm[qi * 68 + d0 + 0]  = acc0;
    *(float4*)&q_sm[qi * 68 + d0 + 4]  = acc1;
    *(float4*)&q_sm[qi * 68 + d0 + 8]  = acc2;
    *(float4*)&q_sm[qi * 68 + d0 + 12] = acc3;
    __syncthreads();

    // ---- pooled partial: sum over the 64 queries in this tile ----
    const int d    = tid & 63;
    const int part = tid >> 6;
    float s = 0.f;
    #pragma unroll
    for (int r = part * 16; r < part * 16 + 16; r++)
        s += q_sm[r * 68 + d];
    a_sm[part * 64 + d] = s;
    __syncthreads();
    if (tid < 64) {
        float tot = a_sm[tid] + a_sm[64 + tid] + a_sm[128 + tid] + a_sm[192 + tid];
        g_part[((b * NTILE) + tile) * DM + h * HD + tid] = tot;
    }
}

// ---------------------------------------------------------------------------
// Final FC: out[b][o] = relu( (mean_s out_attn)[b] @ Wfc + bfc )
// ---------------------------------------------------------------------------
__global__ __launch_bounds__(256) void fc_kernel(
    const float* __restrict__ Wfc, const float* __restrict__ bfc,
    float* __restrict__ out)
{
    __shared__ float pooled[DM];
    const int b   = blockIdx.y;
    const int tid = threadIdx.x;

    for (int i = tid; i < DM; i += 256) {
        float s = 0.f;
        #pragma unroll
        for (int t = 0; t < NTILE; t++)
            s += g_part[(b * NTILE + t) * DM + i];
        pooled[i] = s * (1.0f / (float)S_LEN);
    }
    __syncthreads();

    const int o = blockIdx.x * 256 + tid;
    float acc = bfc[o];
    for (int i = 0; i < DM; i++)
        acc = fmaf(pooled[i], Wfc[i * DM + o], acc);
    out[b * DM + o] = fmaxf(acc, 0.f);
}

// ---------------------------------------------------------------------------
extern "C" void kernel_launch(void* const* d_in, const int* in_sizes, int n_in,
                              void* d_out, int out_size)
{
    const float* x   = (const float*)d_in[0];
    const float* Wq  = (const float*)d_in[1];
    const float* bq  = (const float*)d_in[2];
    const float* Wk  = (const float*)d_in[3];
    const float* bk  = (const float*)d_in[4];
    const float* Wv  = (const float*)d_in[5];
    const float* bv  = (const float*)d_in[6];
    const float* Wfc = (const float*)d_in[7];
    const float* bfc = (const float*)d_in[8];
    float* out = (float*)d_out;

    // QKV projections: 128x128 tiles
    dim3 gg(DM / 128, (BATCH * S_LEN) / 128, 3);
    qkv_gemm<<<gg, 256>>>(x, Wq, bq, Wk, bk, Wv, bv);

    // Windowed attention + per-tile pooling (104448 B dynamic smem)
    const int attn_smem = (64 + 128 + 128 + 64) * 68 * (int)sizeof(float);
    cudaFuncSetAttribute(attn_kernel,
                         cudaFuncAttributeMaxDynamicSharedMemorySize, attn_smem);
    attn_kernel<<<dim3(NTILE, NH, BATCH), 256, attn_smem>>>();

    // Pool + FC + relu
    fc_kernel<<<dim3(3, BATCH), 256>>>(Wfc, bfc, out);
}

// round 6
// speedup vs baseline: 1.5441x; 1.5441x over previous
#include <cuda_runtime.h>
#include <cuda_bf16.h>
#include <cstdint>

// Problem constants
#define S_LEN 1024
#define BATCH 2
#define DM    768
#define NH    12
#define HD    64
#define NTILE 16
#define MROWS (BATCH * S_LEN)   // 2048
#define KP    2304              // split-K' = 3*DM  (hi|lo|hi vs hi|hi|lo)
#define NCHUNK (KP / 32)        // 72

// Scratch (device globals — no allocation allowed)
__device__ float g_q[MROWS * DM];
__device__ float g_k[MROWS * DM];
__device__ float g_v[MROWS * DM];
__device__ float g_part[BATCH * NTILE * DM];
__device__ __nv_bfloat16 g_ahl[MROWS * KP];        // A' = [hi | lo | hi]
__device__ __nv_bfloat16 g_wt[3 * DM * KP];        // W'^T = [hi | hi | lo], [n][k']

// ---------------- PTX helpers (portable: ldmatrix + mma.sync) ----------------
__device__ __forceinline__ uint32_t smem_u32(const void* p) {
    uint32_t a;
    asm("{ .reg .u64 t; cvta.to.shared.u64 t, %1; cvt.u32.u64 %0, t; }"
        : "=r"(a) : "l"(p));
    return a;
}
__device__ __forceinline__ void ldsm_x4(uint32_t& r0, uint32_t& r1,
                                        uint32_t& r2, uint32_t& r3, uint32_t addr) {
    asm volatile("ldmatrix.sync.aligned.m8n8.x4.shared.b16 {%0,%1,%2,%3}, [%4];"
                 : "=r"(r0), "=r"(r1), "=r"(r2), "=r"(r3) : "r"(addr));
}
__device__ __forceinline__ void mma16816(float* c, uint32_t a0, uint32_t a1,
                                         uint32_t a2, uint32_t a3,
                                         uint32_t b0, uint32_t b1) {
    asm volatile("mma.sync.aligned.m16n8k16.row.col.f32.bf16.bf16.f32 "
                 "{%0,%1,%2,%3}, {%4,%5,%6,%7}, {%8,%9}, {%0,%1,%2,%3};"
                 : "+f"(c[0]), "+f"(c[1]), "+f"(c[2]), "+f"(c[3])
                 : "r"(a0), "r"(a1), "r"(a2), "r"(a3), "r"(b0), "r"(b1));
}

// ---------------------------------------------------------------------------
// Convert x -> A' = [hi | lo | hi] along K'
// ---------------------------------------------------------------------------
__global__ __launch_bounds__(256) void conv_x(const float* __restrict__ x)
{
    int i = blockIdx.x * 256 + threadIdx.x;
    float a = x[i];
    __nv_bfloat16 hi = __float2bfloat16(a);
    __nv_bfloat16 lo = __float2bfloat16(a - __bfloat162float(hi));
    int m = i / DM;
    int k = i - m * DM;
    __nv_bfloat16* row = g_ahl + (size_t)m * KP;
    row[k]            = hi;
    row[DM + k]       = lo;
    row[2 * DM + k]   = hi;
}

// ---------------------------------------------------------------------------
// Convert + transpose W[k][n] -> Wt[n] = [hi | hi | lo] along K' (per z)
// ---------------------------------------------------------------------------
__global__ __launch_bounds__(256) void conv_w(
    const float* __restrict__ Wq, const float* __restrict__ Wk,
    const float* __restrict__ Wv)
{
    __shared__ float tile[32][33];
    const int z  = blockIdx.z;
    const float* W = (z == 0) ? Wq : (z == 1) ? Wk : Wv;
    __nv_bfloat16* out = g_wt + (size_t)z * DM * KP;
    const int k0 = blockIdx.x * 32;
    const int n0 = blockIdx.y * 32;
    const int tx = threadIdx.x;      // 0..31
    const int ty = threadIdx.y;      // 0..7

    #pragma unroll
    for (int r = ty; r < 32; r += 8)
        tile[r][tx] = W[(k0 + r) * DM + n0 + tx];
    __syncthreads();
    #pragma unroll
    for (int r = ty; r < 32; r += 8) {
        float v = tile[tx][r];      // W[k0+tx][n0+r]
        __nv_bfloat16 hi = __float2bfloat16(v);
        __nv_bfloat16 lo = __float2bfloat16(v - __bfloat162float(hi));
        __nv_bfloat16* row = out + (size_t)(n0 + r) * KP;
        row[k0 + tx]            = hi;
        row[DM + k0 + tx]       = hi;
        row[2 * DM + k0 + tx]   = lo;
    }
}

// ---------------------------------------------------------------------------
// bf16 HMMA GEMM: C[2048x768] = A'[2048x2304] @ Wt^T + bias, per z.
// CTA 128x128, BK=32, 8 warps (2x4), warp tile 64x32, mma.sync m16n8k16.
// ---------------------------------------------------------------------------
#define LDA 40

__global__ __launch_bounds__(256, 2) void tc_gemm(
    const float* __restrict__ bq, const float* __restrict__ bk,
    const float* __restrict__ bv)
{
    __shared__ __nv_bfloat16 As[2][128 * LDA];
    __shared__ __nv_bfloat16 Bs[2][128 * LDA];

    const int tid  = threadIdx.x;
    const int warp = tid >> 5;
    const int lane = tid & 31;
    const int wm = warp >> 2;       // 0..1  (M)
    const int wn = warp & 3;        // 0..3  (N)

    const int z  = blockIdx.z;
    const int n0 = blockIdx.x * 128;
    const int m0 = blockIdx.y * 128;
    const float* bias = (z == 0) ? bq : (z == 1) ? bk : bv;
    float* C = (z == 0) ? g_q : (z == 1) ? g_k : g_v;
    const __nv_bfloat16* Wt = g_wt + (size_t)z * DM * KP;

    // Global loader mapping: 512 float4 per tile, 2 per thread
    const int f0   = tid;
    const int row0 = f0 >> 2,  q0 = f0 & 3;
    const int row1 = (f0 + 256) >> 2, q1 = (f0 + 256) & 3;

    const __nv_bfloat16* Ag = g_ahl + (size_t)m0 * KP;
    const __nv_bfloat16* Bg = Wt    + (size_t)n0 * KP;

    // ldmatrix lane addressing (bf16-element offsets within a tile)
    const int a_r = lane & 15, a_c = (lane >> 4) * 8;
    const int b_n = (lane & 7) + ((lane >> 4) << 3);
    const int b_k = ((lane >> 3) & 1) * 8;

    const uint32_t asm_base = smem_u32(&As[0][0]);
    const uint32_t bsm_base = smem_u32(&Bs[0][0]);
    const uint32_t buf_bytes = 128 * LDA * 2;

    float acc[4][4][4];
    #pragma unroll
    for (int i = 0; i < 4; i++)
        #pragma unroll
        for (int j = 0; j < 4; j++)
            #pragma unroll
            for (int r = 0; r < 4; r++) acc[i][j][r] = 0.0f;

    // Prologue: chunk 0 -> buffer 0
    {
        *(float4*)&As[0][row0 * LDA + q0 * 8] = *(const float4*)(Ag + (size_t)row0 * KP + q0 * 8);
        *(float4*)&As[0][row1 * LDA + q1 * 8] = *(const float4*)(Ag + (size_t)row1 * KP + q1 * 8);
        *(float4*)&Bs[0][row0 * LDA + q0 * 8] = *(const float4*)(Bg + (size_t)row0 * KP + q0 * 8);
        *(float4*)&Bs[0][row1 * LDA + q1 * 8] = *(const float4*)(Bg + (size_t)row1 * KP + q1 * 8);
    }
    __syncthreads();

    int buf = 0;
    for (int c = 0; c < NCHUNK; c++) {
        const bool has_next = (c + 1) < NCHUNK;
        float4 pA0, pA1, pB0, pB1;
        if (has_next) {
            const size_t ko = (size_t)(c + 1) * 32;
            pA0 = *(const float4*)(Ag + (size_t)row0 * KP + ko + q0 * 8);
            pA1 = *(const float4*)(Ag + (size_t)row1 * KP + ko + q1 * 8);
            pB0 = *(const float4*)(Bg + (size_t)row0 * KP + ko + q0 * 8);
            pB1 = *(const float4*)(Bg + (size_t)row1 * KP + ko + q1 * 8);
        }

        const uint32_t ab = asm_base + buf * buf_bytes;
        const uint32_t bb = bsm_base + buf * buf_bytes;
        #pragma unroll
        for (int ks = 0; ks < 2; ks++) {
            const int k0 = ks * 16;
            uint32_t a[4][4];
            #pragma unroll
            for (int mt = 0; mt < 4; mt++) {
                uint32_t addr = ab + ((wm * 64 + mt * 16 + a_r) * LDA + k0 + a_c) * 2;
                ldsm_x4(a[mt][0], a[mt][1], a[mt][2], a[mt][3], addr);
            }
            uint32_t b[2][4];
            #pragma unroll
            for (int np = 0; np < 2; np++) {
                uint32_t addr = bb + ((wn * 32 + np * 16 + b_n) * LDA + k0 + b_k) * 2;
                ldsm_x4(b[np][0], b[np][1], b[np][2], b[np][3], addr);
            }
            #pragma unroll
            for (int mt = 0; mt < 4; mt++)
                #pragma unroll
                for (int nt = 0; nt < 4; nt++)
                    mma16816(acc[mt][nt],
                             a[mt][0], a[mt][1], a[mt][2], a[mt][3],
                             b[nt >> 1][(nt & 1) * 2], b[nt >> 1][(nt & 1) * 2 + 1]);
        }

        if (has_next) {
            const int nb = buf ^ 1;
            *(float4*)&As[nb][row0 * LDA + q0 * 8] = pA0;
            *(float4*)&As[nb][row1 * LDA + q1 * 8] = pA1;
            *(float4*)&Bs[nb][row0 * LDA + q0 * 8] = pB0;
            *(float4*)&Bs[nb][row1 * LDA + q1 * 8] = pB1;
            __syncthreads();
            buf = nb;
        }
    }

    // Epilogue
    const int g  = lane >> 2;
    const int tg = lane & 3;
    #pragma unroll
    for (int mt = 0; mt < 4; mt++) {
        const int row = m0 + wm * 64 + mt * 16 + g;
        float* Crow0 = C + (size_t)row * DM;
        float* Crow1 = C + (size_t)(row + 8) * DM;
        #pragma unroll
        for (int nt = 0; nt < 4; nt++) {
            const int col = n0 + wn * 32 + nt * 8 + tg * 2;
            const float bx = __ldg(&bias[col]);
            const float by = __ldg(&bias[col + 1]);
            float2 v0 = make_float2(acc[mt][nt][0] + bx, acc[mt][nt][1] + by);
            float2 v1 = make_float2(acc[mt][nt][2] + bx, acc[mt][nt][3] + by);
            *(float2*)&Crow0[col] = v0;
            *(float2*)&Crow1[col] = v1;
        }
    }
}

// ---------------------------------------------------------------------------
// Windowed attention per (tile of 64 queries, head, batch) + per-tile pooling.
// ---------------------------------------------------------------------------
__global__ __launch_bounds__(256) void attn_kernel()
{
    const int tile = blockIdx.x;
    const int h    = blockIdx.y;
    const int b    = blockIdx.z;
    const int s0   = tile * 64;
    const int colbase = h * HD;

    extern __shared__ float sm[];
    float* q_sm = sm;                    // 64*68
    float* k_sm = q_sm + 64 * 68;        // 128*68
    float* v_sm = k_sm + 128 * 68;       // 128*68
    float* a_sm = v_sm + 128 * 68;       // 64*68

    const int tid = threadIdx.x;

    for (int i = tid; i < 64 * 16; i += 256) {
        int row = i >> 4;
        int c4  = (i & 15) << 2;
        float4 v = *(const float4*)&g_q[((b * S_LEN) + s0 + row) * DM + colbase + c4];
        *(float4*)&q_sm[row * 68 + c4] = v;
    }
    for (int i = tid; i < 128 * 16; i += 256) {
        int row  = i >> 4;
        int c4   = (i & 15) << 2;
        int srow = s0 - 32 + row;
        float4 kv = make_float4(0.f, 0.f, 0.f, 0.f);
        float4 vv = make_float4(0.f, 0.f, 0.f, 0.f);
        if (srow >= 0 && srow < S_LEN) {
            kv = *(const float4*)&g_k[((b * S_LEN) + srow) * DM + colbase + c4];
            vv = *(const float4*)&g_v[((b * S_LEN) + srow) * DM + colbase + c4];
        }
        *(float4*)&k_sm[row * 68 + c4] = kv;
        *(float4*)&v_sm[row * 68 + c4] = vv;
    }
    __syncthreads();

    const int qi  = tid >> 2;
    const int sub = tid & 3;
    const int sglob = s0 + qi;

    float sc[17];
    const int nw = (sub == 0) ? 17 : 16;
    const float* qr = &q_sm[qi * 68];
    for (int j = 0; j < nw; j++) {
        int w = sub + 4 * j;
        const float* kr = &k_sm[(qi + w) * 68];
        float s = 0.f;
        #pragma unroll
        for (int dc = 0; dc < 16; dc++) {
            float4 qv = *(const float4*)&qr[dc * 4];
            float4 kv = *(const float4*)&kr[dc * 4];
            s = fmaf(qv.x, kv.x, s);
            s = fmaf(qv.y, kv.y, s);
            s = fmaf(qv.z, kv.z, s);
            s = fmaf(qv.w, kv.w, s);
        }
        int ks = sglob - 32 + w;
        sc[j] = (ks >= 0 && ks < S_LEN) ? s * 0.125f : -1e9f;
    }

    float m = -1e30f;
    for (int j = 0; j < nw; j++) m = fmaxf(m, sc[j]);
    m = fmaxf(m, __shfl_xor_sync(0xffffffffu, m, 1));
    m = fmaxf(m, __shfl_xor_sync(0xffffffffu, m, 2));
    float lsum = 0.f;
    for (int j = 0; j < nw; j++) { sc[j] = __expf(sc[j] - m); lsum += sc[j]; }
    lsum += __shfl_xor_sync(0xffffffffu, lsum, 1);
    lsum += __shfl_xor_sync(0xffffffffu, lsum, 2);
    float rinv = 1.0f / lsum;
    for (int j = 0; j < nw; j++)
        a_sm[qi * 68 + sub + 4 * j] = sc[j] * rinv;
    __syncthreads();

    const int d0 = sub * 16;
    float4 acc0 = make_float4(0.f, 0.f, 0.f, 0.f);
    float4 acc1 = acc0, acc2 = acc0, acc3 = acc0;
    const float* ar = &a_sm[qi * 68];
    for (int w = 0; w < 65; w++) {
        float p = ar[w];
        const float* vr = &v_sm[(qi + w) * 68 + d0];
        float4 v0 = *(const float4*)&vr[0];
        float4 v1 = *(const float4*)&vr[4];
        float4 v2 = *(const float4*)&vr[8];
        float4 v3 = *(const float4*)&vr[12];
        acc0.x = fmaf(p, v0.x, acc0.x); acc0.y = fmaf(p, v0.y, acc0.y);
        acc0.z = fmaf(p, v0.z, acc0.z); acc0.w = fmaf(p, v0.w, acc0.w);
        acc1.x = fmaf(p, v1.x, acc1.x); acc1.y = fmaf(p, v1.y, acc1.y);
        acc1.z = fmaf(p, v1.z, acc1.z); acc1.w = fmaf(p, v1.w, acc1.w);
        acc2.x = fmaf(p, v2.x, acc2.x); acc2.y = fmaf(p, v2.y, acc2.y);
        acc2.z = fmaf(p, v2.z, acc2.z); acc2.w = fmaf(p, v2.w, acc2.w);
        acc3.x = fmaf(p, v3.x, acc3.x); acc3.y = fmaf(p, v3.y, acc3.y);
        acc3.z = fmaf(p, v3.z, acc3.z); acc3.w = fmaf(p, v3.w, acc3.w);
    }

    *(float4*)&q_sm[qi * 68 + d0 + 0]  = acc0;
    *(float4*)&q_sm[qi * 68 + d0 + 4]  = acc1;
    *(float4*)&q_sm[qi * 68 + d0 + 8]  = acc2;
    *(float4*)&q_sm[qi * 68 + d0 + 12] = acc3;
    __syncthreads();

    const int d    = tid & 63;
    const int part = tid >> 6;
    float s = 0.f;
    #pragma unroll
    for (int r = part * 16; r < part * 16 + 16; r++)
        s += q_sm[r * 68 + d];
    a_sm[part * 64 + d] = s;
    __syncthreads();
    if (tid < 64) {
        float tot = a_sm[tid] + a_sm[64 + tid] + a_sm[128 + tid] + a_sm[192 + tid];
        g_part[((b * NTILE) + tile) * DM + h * HD + tid] = tot;
    }
}

// ---------------------------------------------------------------------------
__global__ __launch_bounds__(256) void fc_kernel(
    const float* __restrict__ Wfc, const float* __restrict__ bfc,
    float* __restrict__ out)
{
    __shared__ float pooled[DM];
    const int b   = blockIdx.y;
    const int tid = threadIdx.x;

    for (int i = tid; i < DM; i += 256) {
        float s = 0.f;
        #pragma unroll
        for (int t = 0; t < NTILE; t++)
            s += g_part[(b * NTILE + t) * DM + i];
        pooled[i] = s * (1.0f / (float)S_LEN);
    }
    __syncthreads();

    const int o = blockIdx.x * 256 + tid;
    float acc = bfc[o];
    for (int i = 0; i < DM; i++)
        acc = fmaf(pooled[i], Wfc[i * DM + o], acc);
    out[b * DM + o] = fmaxf(acc, 0.f);
}

// ---------------------------------------------------------------------------
extern "C" void kernel_launch(void* const* d_in, const int* in_sizes, int n_in,
                              void* d_out, int out_size)
{
    const float* x   = (const float*)d_in[0];
    const float* Wq  = (const float*)d_in[1];
    const float* bq  = (const float*)d_in[2];
    const float* Wk  = (const float*)d_in[3];
    const float* bk  = (const float*)d_in[4];
    const float* Wv  = (const float*)d_in[5];
    const float* bv  = (const float*)d_in[6];
    const float* Wfc = (const float*)d_in[7];
    const float* bfc = (const float*)d_in[8];
    float* out = (float*)d_out;

    // bf16 3-term split conversion
    conv_x<<<(MROWS * DM) / 256, 256>>>(x);
    conv_w<<<dim3(DM / 32, DM / 32, 3), dim3(32, 8)>>>(Wq, Wk, Wv);

    // HMMA GEMMs (static smem only)
    tc_gemm<<<dim3(DM / 128, MROWS / 128, 3), 256>>>(bq, bk, bv);

    // Windowed attention + per-tile pooling
    const int attn_smem = (64 + 128 + 128 + 64) * 68 * (int)sizeof(float);
    cudaFuncSetAttribute(attn_kernel,
                         cudaFuncAttributeMaxDynamicSharedMemorySize, attn_smem);
    attn_kernel<<<dim3(NTILE, NH, BATCH), 256, attn_smem>>>();

    fc_kernel<<<dim3(3, BATCH), 256>>>(Wfc, bfc, out);
}

// round 7
// speedup vs baseline: 1.6545x; 1.0715x over previous
#include <cuda_runtime.h>
#include <cuda_bf16.h>
#include <cstdint>

// Problem constants
#define S_LEN 1024
#define BATCH 2
#define DM    768
#define NH    12
#define HD    64
#define NTILE 16
#define MROWS (BATCH * S_LEN)   // 2048
#define KP    2304              // split-K' = 3*DM  (hi|lo|hi vs hi|hi|lo)
#define NCHUNK (KP / 32)        // 72

// Scratch (device globals — no allocation allowed)
__device__ float g_q[MROWS * DM];
__device__ float g_k[MROWS * DM];
__device__ float g_v[MROWS * DM];
__device__ float g_part[BATCH * NTILE * DM];
__device__ __nv_bfloat16 g_ahl[MROWS * KP];        // A' = [hi | lo | hi]
__device__ __nv_bfloat16 g_wt[3 * DM * KP];        // W'^T = [hi | hi | lo], [n][k']

// ---------------- PTX helpers (portable: ldmatrix + mma.sync) ----------------
__device__ __forceinline__ uint32_t smem_u32(const void* p) {
    uint32_t a;
    asm("{ .reg .u64 t; cvta.to.shared.u64 t, %1; cvt.u32.u64 %0, t; }"
        : "=r"(a) : "l"(p));
    return a;
}
__device__ __forceinline__ void ldsm_x4(uint32_t& r0, uint32_t& r1,
                                        uint32_t& r2, uint32_t& r3, uint32_t addr) {
    asm volatile("ldmatrix.sync.aligned.m8n8.x4.shared.b16 {%0,%1,%2,%3}, [%4];"
                 : "=r"(r0), "=r"(r1), "=r"(r2), "=r"(r3) : "r"(addr));
}
__device__ __forceinline__ void mma16816(float* c, uint32_t a0, uint32_t a1,
                                         uint32_t a2, uint32_t a3,
                                         uint32_t b0, uint32_t b1) {
    asm volatile("mma.sync.aligned.m16n8k16.row.col.f32.bf16.bf16.f32 "
                 "{%0,%1,%2,%3}, {%4,%5,%6,%7}, {%8,%9}, {%0,%1,%2,%3};"
                 : "+f"(c[0]), "+f"(c[1]), "+f"(c[2]), "+f"(c[3])
                 : "r"(a0), "r"(a1), "r"(a2), "r"(a3), "r"(b0), "r"(b1));
}

// ---------------------------------------------------------------------------
// Convert x -> A' = [hi | lo | hi] along K'
// ---------------------------------------------------------------------------
__global__ __launch_bounds__(256) void conv_x(const float* __restrict__ x)
{
    int i = blockIdx.x * 256 + threadIdx.x;
    float a = x[i];
    __nv_bfloat16 hi = __float2bfloat16(a);
    __nv_bfloat16 lo = __float2bfloat16(a - __bfloat162float(hi));
    int m = i / DM;
    int k = i - m * DM;
    __nv_bfloat16* row = g_ahl + (size_t)m * KP;
    row[k]            = hi;
    row[DM + k]       = lo;
    row[2 * DM + k]   = hi;
}

// ---------------------------------------------------------------------------
// Convert + transpose W[k][n] -> Wt[n] = [hi | hi | lo] along K' (per z)
// ---------------------------------------------------------------------------
__global__ __launch_bounds__(256) void conv_w(
    const float* __restrict__ Wq, const float* __restrict__ Wk,
    const float* __restrict__ Wv)
{
    __shared__ float tile[32][33];
    const int z  = blockIdx.z;
    const float* W = (z == 0) ? Wq : (z == 1) ? Wk : Wv;
    __nv_bfloat16* out = g_wt + (size_t)z * DM * KP;
    const int k0 = blockIdx.x * 32;
    const int n0 = blockIdx.y * 32;
    const int tx = threadIdx.x;
    const int ty = threadIdx.y;

    #pragma unroll
    for (int r = ty; r < 32; r += 8)
        tile[r][tx] = W[(k0 + r) * DM + n0 + tx];
    __syncthreads();
    #pragma unroll
    for (int r = ty; r < 32; r += 8) {
        float v = tile[tx][r];
        __nv_bfloat16 hi = __float2bfloat16(v);
        __nv_bfloat16 lo = __float2bfloat16(v - __bfloat162float(hi));
        __nv_bfloat16* row = out + (size_t)(n0 + r) * KP;
        row[k0 + tx]            = hi;
        row[DM + k0 + tx]       = hi;
        row[2 * DM + k0 + tx]   = lo;
    }
}

// ---------------------------------------------------------------------------
// bf16 HMMA GEMM: C[2048x768] = A'[2048x2304] @ Wt^T + bias, per z.
// ---------------------------------------------------------------------------
#define LDA 40

__global__ __launch_bounds__(256, 2) void tc_gemm(
    const float* __restrict__ bq, const float* __restrict__ bk,
    const float* __restrict__ bv)
{
    __shared__ __nv_bfloat16 As[2][128 * LDA];
    __shared__ __nv_bfloat16 Bs[2][128 * LDA];

    const int tid  = threadIdx.x;
    const int warp = tid >> 5;
    const int lane = tid & 31;
    const int wm = warp >> 2;
    const int wn = warp & 3;

    const int z  = blockIdx.z;
    const int n0 = blockIdx.x * 128;
    const int m0 = blockIdx.y * 128;
    const float* bias = (z == 0) ? bq : (z == 1) ? bk : bv;
    float* C = (z == 0) ? g_q : (z == 1) ? g_k : g_v;
    const __nv_bfloat16* Wt = g_wt + (size_t)z * DM * KP;

    const int f0   = tid;
    const int row0 = f0 >> 2,  q0 = f0 & 3;
    const int row1 = (f0 + 256) >> 2, q1 = (f0 + 256) & 3;

    const __nv_bfloat16* Ag = g_ahl + (size_t)m0 * KP;
    const __nv_bfloat16* Bg = Wt    + (size_t)n0 * KP;

    const int a_r = lane & 15, a_c = (lane >> 4) * 8;
    const int b_n = (lane & 7) + ((lane >> 4) << 3);
    const int b_k = ((lane >> 3) & 1) * 8;

    const uint32_t asm_base = smem_u32(&As[0][0]);
    const uint32_t bsm_base = smem_u32(&Bs[0][0]);
    const uint32_t buf_bytes = 128 * LDA * 2;

    float acc[4][4][4];
    #pragma unroll
    for (int i = 0; i < 4; i++)
        #pragma unroll
        for (int j = 0; j < 4; j++)
            #pragma unroll
            for (int r = 0; r < 4; r++) acc[i][j][r] = 0.0f;

    {
        *(float4*)&As[0][row0 * LDA + q0 * 8] = *(const float4*)(Ag + (size_t)row0 * KP + q0 * 8);
        *(float4*)&As[0][row1 * LDA + q1 * 8] = *(const float4*)(Ag + (size_t)row1 * KP + q1 * 8);
        *(float4*)&Bs[0][row0 * LDA + q0 * 8] = *(const float4*)(Bg + (size_t)row0 * KP + q0 * 8);
        *(float4*)&Bs[0][row1 * LDA + q1 * 8] = *(const float4*)(Bg + (size_t)row1 * KP + q1 * 8);
    }
    __syncthreads();

    int buf = 0;
    for (int c = 0; c < NCHUNK; c++) {
        const bool has_next = (c + 1) < NCHUNK;
        float4 pA0, pA1, pB0, pB1;
        if (has_next) {
            const size_t ko = (size_t)(c + 1) * 32;
            pA0 = *(const float4*)(Ag + (size_t)row0 * KP + ko + q0 * 8);
            pA1 = *(const float4*)(Ag + (size_t)row1 * KP + ko + q1 * 8);
            pB0 = *(const float4*)(Bg + (size_t)row0 * KP + ko + q0 * 8);
            pB1 = *(const float4*)(Bg + (size_t)row1 * KP + ko + q1 * 8);
        }

        const uint32_t ab = asm_base + buf * buf_bytes;
        const uint32_t bb = bsm_base + buf * buf_bytes;
        #pragma unroll
        for (int ks = 0; ks < 2; ks++) {
            const int k0 = ks * 16;
            uint32_t a[4][4];
            #pragma unroll
            for (int mt = 0; mt < 4; mt++) {
                uint32_t addr = ab + ((wm * 64 + mt * 16 + a_r) * LDA + k0 + a_c) * 2;
                ldsm_x4(a[mt][0], a[mt][1], a[mt][2], a[mt][3], addr);
            }
            uint32_t b[2][4];
            #pragma unroll
            for (int np = 0; np < 2; np++) {
                uint32_t addr = bb + ((wn * 32 + np * 16 + b_n) * LDA + k0 + b_k) * 2;
                ldsm_x4(b[np][0], b[np][1], b[np][2], b[np][3], addr);
            }
            #pragma unroll
            for (int mt = 0; mt < 4; mt++)
                #pragma unroll
                for (int nt = 0; nt < 4; nt++)
                    mma16816(acc[mt][nt],
                             a[mt][0], a[mt][1], a[mt][2], a[mt][3],
                             b[nt >> 1][(nt & 1) * 2], b[nt >> 1][(nt & 1) * 2 + 1]);
        }

        if (has_next) {
            const int nb = buf ^ 1;
            *(float4*)&As[nb][row0 * LDA + q0 * 8] = pA0;
            *(float4*)&As[nb][row1 * LDA + q1 * 8] = pA1;
            *(float4*)&Bs[nb][row0 * LDA + q0 * 8] = pB0;
            *(float4*)&Bs[nb][row1 * LDA + q1 * 8] = pB1;
            __syncthreads();
            buf = nb;
        }
    }

    const int g  = lane >> 2;
    const int tg = lane & 3;
    #pragma unroll
    for (int mt = 0; mt < 4; mt++) {
        const int row = m0 + wm * 64 + mt * 16 + g;
        float* Crow0 = C + (size_t)row * DM;
        float* Crow1 = C + (size_t)(row + 8) * DM;
        #pragma unroll
        for (int nt = 0; nt < 4; nt++) {
            const int col = n0 + wn * 32 + nt * 8 + tg * 2;
            const float bx = __ldg(&bias[col]);
            const float by = __ldg(&bias[col + 1]);
            float2 v0 = make_float2(acc[mt][nt][0] + bx, acc[mt][nt][1] + by);
            float2 v1 = make_float2(acc[mt][nt][2] + bx, acc[mt][nt][3] + by);
            *(float2*)&Crow0[col] = v0;
            *(float2*)&Crow1[col] = v1;
        }
    }
}

// ---------------------------------------------------------------------------
// Windowed attention, v2: 512 threads, 8 lanes/query, smem 87KB (2 CTAs/SM).
// q_sm reused for attn weights (row-private), k_sm for out rows, v_sm for
// pool partials.
// ---------------------------------------------------------------------------
__global__ __launch_bounds__(512, 2) void attn_kernel()
{
    const int tile = blockIdx.x;
    const int h    = blockIdx.y;
    const int b    = blockIdx.z;
    const int s0   = tile * 64;
    const int colbase = h * HD;

    extern __shared__ float sm[];
    float* q_sm = sm;                    // 64*68   (then attn weights)
    float* k_sm = q_sm + 64 * 68;        // 128*68  (then out rows)
    float* v_sm = k_sm + 128 * 68;       // 128*68  (then pool partials)

    const int tid = threadIdx.x;

    // Load Q tile
    for (int i = tid; i < 64 * 16; i += 512) {
        int row = i >> 4;
        int c4  = (i & 15) << 2;
        float4 v = *(const float4*)&g_q[((b * S_LEN) + s0 + row) * DM + colbase + c4];
        *(float4*)&q_sm[row * 68 + c4] = v;
    }
    // Load K/V window (rows s0-32 .. s0+95), zero-fill out of range
    for (int i = tid; i < 128 * 16; i += 512) {
        int row  = i >> 4;
        int c4   = (i & 15) << 2;
        int srow = s0 - 32 + row;
        float4 kv = make_float4(0.f, 0.f, 0.f, 0.f);
        float4 vv = make_float4(0.f, 0.f, 0.f, 0.f);
        if (srow >= 0 && srow < S_LEN) {
            kv = *(const float4*)&g_k[((b * S_LEN) + srow) * DM + colbase + c4];
            vv = *(const float4*)&g_v[((b * S_LEN) + srow) * DM + colbase + c4];
        }
        *(float4*)&k_sm[row * 68 + c4] = kv;
        *(float4*)&v_sm[row * 68 + c4] = vv;
    }
    __syncthreads();

    const int qi  = tid >> 3;       // 0..63 query within tile
    const int sub = tid & 7;        // 0..7  lane within query group
    const int sglob = s0 + qi;

    // ---- scores: lane handles w = sub, sub+8, ..., (9 slots, clamped) ----
    int ro[9];
    #pragma unroll
    for (int j = 0; j < 9; j++) {
        int w = sub + 8 * j;
        if (w > 64) w = 64;         // clamp keeps reads in-bounds; masked later
        ro[j] = (qi + w) * 68;
    }
    float sc[9];
    #pragma unroll
    for (int j = 0; j < 9; j++) sc[j] = 0.f;

    #pragma unroll
    for (int dc = 0; dc < 16; dc++) {
        float4 qv = *(const float4*)&q_sm[qi * 68 + dc * 4];
        #pragma unroll
        for (int j = 0; j < 9; j++) {
            float4 kv = *(const float4*)&k_sm[ro[j] + dc * 4];
            sc[j] = fmaf(qv.x, kv.x, sc[j]);
            sc[j] = fmaf(qv.y, kv.y, sc[j]);
            sc[j] = fmaf(qv.z, kv.z, sc[j]);
            sc[j] = fmaf(qv.w, kv.w, sc[j]);
        }
    }

    // mask + softmax over the 8-lane group
    #pragma unroll
    for (int j = 0; j < 9; j++) {
        int w  = sub + 8 * j;
        int ks = sglob - 32 + w;
        bool valid = (w <= 64) && (ks >= 0) && (ks < S_LEN);
        sc[j] = valid ? sc[j] * 0.125f : -1e9f;
    }
    float m = -1e30f;
    #pragma unroll
    for (int j = 0; j < 9; j++) m = fmaxf(m, sc[j]);
    m = fmaxf(m, __shfl_xor_sync(0xffffffffu, m, 1));
    m = fmaxf(m, __shfl_xor_sync(0xffffffffu, m, 2));
    m = fmaxf(m, __shfl_xor_sync(0xffffffffu, m, 4));
    float lsum = 0.f;
    #pragma unroll
    for (int j = 0; j < 9; j++) { sc[j] = __expf(sc[j] - m); lsum += sc[j]; }
    lsum += __shfl_xor_sync(0xffffffffu, lsum, 1);
    lsum += __shfl_xor_sync(0xffffffffu, lsum, 2);
    lsum += __shfl_xor_sync(0xffffffffu, lsum, 4);
    const float rinv = 1.0f / lsum;

    // attn weights -> q_sm row qi (row-private to this 8-lane group)
    #pragma unroll
    for (int j = 0; j < 9; j++) {
        int w = sub + 8 * j;
        if (w <= 64) q_sm[qi * 68 + w] = sc[j] * rinv;
    }
    __syncwarp();

    // ---- AV: out[qi][sub*8 .. sub*8+7] ----
    const int d0 = sub * 8;
    float4 acc0 = make_float4(0.f, 0.f, 0.f, 0.f);
    float4 acc1 = acc0;
    const float* ar = &q_sm[qi * 68];
    for (int w = 0; w < 65; w++) {
        float p = ar[w];
        const float* vr = &v_sm[(qi + w) * 68 + d0];
        float4 v0 = *(const float4*)&vr[0];
        float4 v1 = *(const float4*)&vr[4];
        acc0.x = fmaf(p, v0.x, acc0.x); acc0.y = fmaf(p, v0.y, acc0.y);
        acc0.z = fmaf(p, v0.z, acc0.z); acc0.w = fmaf(p, v0.w, acc0.w);
        acc1.x = fmaf(p, v1.x, acc1.x); acc1.y = fmaf(p, v1.y, acc1.y);
        acc1.z = fmaf(p, v1.z, acc1.z); acc1.w = fmaf(p, v1.w, acc1.w);
    }

    __syncthreads();     // all score/AV reads of k_sm & v_sm complete
    *(float4*)&k_sm[qi * 68 + d0 + 0] = acc0;
    *(float4*)&k_sm[qi * 68 + d0 + 4] = acc1;
    __syncthreads();

    // ---- pooled partial: 8 parts x 8 rows each ----
    const int d    = tid & 63;
    const int part = tid >> 6;          // 0..7
    float s = 0.f;
    #pragma unroll
    for (int r = part * 8; r < part * 8 + 8; r++)
        s += k_sm[r * 68 + d];
    v_sm[part * 64 + d] = s;
    __syncthreads();
    if (tid < 64) {
        float tot = 0.f;
        #pragma unroll
        for (int p = 0; p < 8; p++) tot += v_sm[p * 64 + tid];
        g_part[((b * NTILE) + tile) * DM + h * HD + tid] = tot;
    }
}

// ---------------------------------------------------------------------------
__global__ __launch_bounds__(256) void fc_kernel(
    const float* __restrict__ Wfc, const float* __restrict__ bfc,
    float* __restrict__ out)
{
    __shared__ float pooled[DM];
    const int b   = blockIdx.y;
    const int tid = threadIdx.x;

    for (int i = tid; i < DM; i += 256) {
        float s = 0.f;
        #pragma unroll
        for (int t = 0; t < NTILE; t++)
            s += g_part[(b * NTILE + t) * DM + i];
        pooled[i] = s * (1.0f / (float)S_LEN);
    }
    __syncthreads();

    const int o = blockIdx.x * 256 + tid;
    float acc = bfc[o];
    for (int i = 0; i < DM; i++)
        acc = fmaf(pooled[i], Wfc[i * DM + o], acc);
    out[b * DM + o] = fmaxf(acc, 0.f);
}

// ---------------------------------------------------------------------------
extern "C" void kernel_launch(void* const* d_in, const int* in_sizes, int n_in,
                              void* d_out, int out_size)
{
    const float* x   = (const float*)d_in[0];
    const float* Wq  = (const float*)d_in[1];
    const float* bq  = (const float*)d_in[2];
    const float* Wk  = (const float*)d_in[3];
    const float* bk  = (const float*)d_in[4];
    const float* Wv  = (const float*)d_in[5];
    const float* bv  = (const float*)d_in[6];
    const float* Wfc = (const float*)d_in[7];
    const float* bfc = (const float*)d_in[8];
    float* out = (float*)d_out;

    // bf16 3-term split conversion
    conv_x<<<(MROWS * DM) / 256, 256>>>(x);
    conv_w<<<dim3(DM / 32, DM / 32, 3), dim3(32, 8)>>>(Wq, Wk, Wv);

    // HMMA GEMMs
    tc_gemm<<<dim3(DM / 128, MROWS / 128, 3), 256>>>(bq, bk, bv);

    // Windowed attention + per-tile pooling (87040 B dynamic smem)
    const int attn_smem = (64 + 128 + 128) * 68 * (int)sizeof(float);
    cudaFuncSetAttribute(attn_kernel,
                         cudaFuncAttributeMaxDynamicSharedMemorySize, attn_smem);
    attn_kernel<<<dim3(NTILE, NH, BATCH), 512, attn_smem>>>();

    fc_kernel<<<dim3(3, BATCH), 256>>>(Wfc, bfc, out);
}

// round 8
// speedup vs baseline: 1.8565x; 1.1221x over previous
#include <cuda_runtime.h>
#include <cuda_bf16.h>
#include <cstdint>

// Problem constants
#define S_LEN 1024
#define BATCH 2
#define DM    768
#define NH    12
#define HD    64
#define NTILE 16
#define MROWS (BATCH * S_LEN)   // 2048
#define KP    2304              // split-K' = 3*DM  (hi|lo|hi vs hi|hi|lo)
#define NCHUNK (KP / 32)        // 72

// Scratch (device globals — no allocation allowed)
__device__ float g_q[MROWS * DM];
__device__ float g_k[MROWS * DM];
__device__ float g_v[MROWS * DM];
__device__ float g_part[BATCH * NTILE * DM];
__device__ __nv_bfloat16 g_ahl[MROWS * KP];        // A' = [hi | lo | hi]
__device__ __nv_bfloat16 g_wt[3 * DM * KP];        // W'^T = [hi | hi | lo], [n][k']

// ---------------- PTX helpers (portable: ldmatrix + mma.sync) ----------------
__device__ __forceinline__ uint32_t smem_u32(const void* p) {
    uint32_t a;
    asm("{ .reg .u64 t; cvta.to.shared.u64 t, %1; cvt.u32.u64 %0, t; }"
        : "=r"(a) : "l"(p));
    return a;
}
__device__ __forceinline__ void ldsm_x4(uint32_t& r0, uint32_t& r1,
                                        uint32_t& r2, uint32_t& r3, uint32_t addr) {
    asm volatile("ldmatrix.sync.aligned.m8n8.x4.shared.b16 {%0,%1,%2,%3}, [%4];"
                 : "=r"(r0), "=r"(r1), "=r"(r2), "=r"(r3) : "r"(addr));
}
__device__ __forceinline__ void mma16816(float* c, uint32_t a0, uint32_t a1,
                                         uint32_t a2, uint32_t a3,
                                         uint32_t b0, uint32_t b1) {
    asm volatile("mma.sync.aligned.m16n8k16.row.col.f32.bf16.bf16.f32 "
                 "{%0,%1,%2,%3}, {%4,%5,%6,%7}, {%8,%9}, {%0,%1,%2,%3};"
                 : "+f"(c[0]), "+f"(c[1]), "+f"(c[2]), "+f"(c[3])
                 : "r"(a0), "r"(a1), "r"(a2), "r"(a3), "r"(b0), "r"(b1));
}

// ---------------------------------------------------------------------------
// Convert x -> A' = [hi | lo | hi] along K'
// ---------------------------------------------------------------------------
__global__ __launch_bounds__(256) void conv_x(const float* __restrict__ x)
{
    int i = blockIdx.x * 256 + threadIdx.x;
    float a = x[i];
    __nv_bfloat16 hi = __float2bfloat16(a);
    __nv_bfloat16 lo = __float2bfloat16(a - __bfloat162float(hi));
    int m = i / DM;
    int k = i - m * DM;
    __nv_bfloat16* row = g_ahl + (size_t)m * KP;
    row[k]            = hi;
    row[DM + k]       = lo;
    row[2 * DM + k]   = hi;
}

// ---------------------------------------------------------------------------
// Convert + transpose W[k][n] -> Wt[n] = [hi | hi | lo] along K' (per z)
// ---------------------------------------------------------------------------
__global__ __launch_bounds__(256) void conv_w(
    const float* __restrict__ Wq, const float* __restrict__ Wk,
    const float* __restrict__ Wv)
{
    __shared__ float tile[32][33];
    const int z  = blockIdx.z;
    const float* W = (z == 0) ? Wq : (z == 1) ? Wk : Wv;
    __nv_bfloat16* out = g_wt + (size_t)z * DM * KP;
    const int k0 = blockIdx.x * 32;
    const int n0 = blockIdx.y * 32;
    const int tx = threadIdx.x;
    const int ty = threadIdx.y;

    #pragma unroll
    for (int r = ty; r < 32; r += 8)
        tile[r][tx] = W[(k0 + r) * DM + n0 + tx];
    __syncthreads();
    #pragma unroll
    for (int r = ty; r < 32; r += 8) {
        float v = tile[tx][r];
        __nv_bfloat16 hi = __float2bfloat16(v);
        __nv_bfloat16 lo = __float2bfloat16(v - __bfloat162float(hi));
        __nv_bfloat16* row = out + (size_t)(n0 + r) * KP;
        row[k0 + tx]            = hi;
        row[DM + k0 + tx]       = hi;
        row[2 * DM + k0 + tx]   = lo;
    }
}

// ---------------------------------------------------------------------------
// bf16 HMMA GEMM: C[2048x768] = A'[2048x2304] @ Wt^T + bias, per z.
// ---------------------------------------------------------------------------
#define LDA 40

__global__ __launch_bounds__(256, 2) void tc_gemm(
    const float* __restrict__ bq, const float* __restrict__ bk,
    const float* __restrict__ bv)
{
    __shared__ __nv_bfloat16 As[2][128 * LDA];
    __shared__ __nv_bfloat16 Bs[2][128 * LDA];

    const int tid  = threadIdx.x;
    const int warp = tid >> 5;
    const int lane = tid & 31;
    const int wm = warp >> 2;
    const int wn = warp & 3;

    const int z  = blockIdx.z;
    const int n0 = blockIdx.x * 128;
    const int m0 = blockIdx.y * 128;
    const float* bias = (z == 0) ? bq : (z == 1) ? bk : bv;
    float* C = (z == 0) ? g_q : (z == 1) ? g_k : g_v;
    const __nv_bfloat16* Wt = g_wt + (size_t)z * DM * KP;

    const int f0   = tid;
    const int row0 = f0 >> 2,  q0 = f0 & 3;
    const int row1 = (f0 + 256) >> 2, q1 = (f0 + 256) & 3;

    const __nv_bfloat16* Ag = g_ahl + (size_t)m0 * KP;
    const __nv_bfloat16* Bg = Wt    + (size_t)n0 * KP;

    const int a_r = lane & 15, a_c = (lane >> 4) * 8;
    const int b_n = (lane & 7) + ((lane >> 4) << 3);
    const int b_k = ((lane >> 3) & 1) * 8;

    const uint32_t asm_base = smem_u32(&As[0][0]);
    const uint32_t bsm_base = smem_u32(&Bs[0][0]);
    const uint32_t buf_bytes = 128 * LDA * 2;

    float acc[4][4][4];
    #pragma unroll
    for (int i = 0; i < 4; i++)
        #pragma unroll
        for (int j = 0; j < 4; j++)
            #pragma unroll
            for (int r = 0; r < 4; r++) acc[i][j][r] = 0.0f;

    {
        *(float4*)&As[0][row0 * LDA + q0 * 8] = *(const float4*)(Ag + (size_t)row0 * KP + q0 * 8);
        *(float4*)&As[0][row1 * LDA + q1 * 8] = *(const float4*)(Ag + (size_t)row1 * KP + q1 * 8);
        *(float4*)&Bs[0][row0 * LDA + q0 * 8] = *(const float4*)(Bg + (size_t)row0 * KP + q0 * 8);
        *(float4*)&Bs[0][row1 * LDA + q1 * 8] = *(const float4*)(Bg + (size_t)row1 * KP + q1 * 8);
    }
    __syncthreads();

    int buf = 0;
    for (int c = 0; c < NCHUNK; c++) {
        const bool has_next = (c + 1) < NCHUNK;
        float4 pA0, pA1, pB0, pB1;
        if (has_next) {
            const size_t ko = (size_t)(c + 1) * 32;
            pA0 = *(const float4*)(Ag + (size_t)row0 * KP + ko + q0 * 8);
            pA1 = *(const float4*)(Ag + (size_t)row1 * KP + ko + q1 * 8);
            pB0 = *(const float4*)(Bg + (size_t)row0 * KP + ko + q0 * 8);
            pB1 = *(const float4*)(Bg + (size_t)row1 * KP + ko + q1 * 8);
        }

        const uint32_t ab = asm_base + buf * buf_bytes;
        const uint32_t bb = bsm_base + buf * buf_bytes;
        #pragma unroll
        for (int ks = 0; ks < 2; ks++) {
            const int k0 = ks * 16;
            uint32_t a[4][4];
            #pragma unroll
            for (int mt = 0; mt < 4; mt++) {
                uint32_t addr = ab + ((wm * 64 + mt * 16 + a_r) * LDA + k0 + a_c) * 2;
                ldsm_x4(a[mt][0], a[mt][1], a[mt][2], a[mt][3], addr);
            }
            uint32_t b[2][4];
            #pragma unroll
            for (int np = 0; np < 2; np++) {
                uint32_t addr = bb + ((wn * 32 + np * 16 + b_n) * LDA + k0 + b_k) * 2;
                ldsm_x4(b[np][0], b[np][1], b[np][2], b[np][3], addr);
            }
            #pragma unroll
            for (int mt = 0; mt < 4; mt++)
                #pragma unroll
                for (int nt = 0; nt < 4; nt++)
                    mma16816(acc[mt][nt],
                             a[mt][0], a[mt][1], a[mt][2], a[mt][3],
                             b[nt >> 1][(nt & 1) * 2], b[nt >> 1][(nt & 1) * 2 + 1]);
        }

        if (has_next) {
            const int nb = buf ^ 1;
            *(float4*)&As[nb][row0 * LDA + q0 * 8] = pA0;
            *(float4*)&As[nb][row1 * LDA + q1 * 8] = pA1;
            *(float4*)&Bs[nb][row0 * LDA + q0 * 8] = pB0;
            *(float4*)&Bs[nb][row1 * LDA + q1 * 8] = pB1;
            __syncthreads();
            buf = nb;
        }
    }

    const int g  = lane >> 2;
    const int tg = lane & 3;
    #pragma unroll
    for (int mt = 0; mt < 4; mt++) {
        const int row = m0 + wm * 64 + mt * 16 + g;
        float* Crow0 = C + (size_t)row * DM;
        float* Crow1 = C + (size_t)(row + 8) * DM;
        #pragma unroll
        for (int nt = 0; nt < 4; nt++) {
            const int col = n0 + wn * 32 + nt * 8 + tg * 2;
            const float bx = __ldg(&bias[col]);
            const float by = __ldg(&bias[col + 1]);
            float2 v0 = make_float2(acc[mt][nt][0] + bx, acc[mt][nt][1] + by);
            float2 v1 = make_float2(acc[mt][nt][2] + bx, acc[mt][nt][3] + by);
            *(float2*)&Crow0[col] = v0;
            *(float2*)&Crow1[col] = v1;
        }
    }
}

// ---------------------------------------------------------------------------
// Windowed attention, v3: 256 threads, 8-lane group handles TWO adjacent
// queries — every k/v smem row load feeds both queries (halves LDS traffic).
// q_sm rows reused for attn weights; k_sm rows reused for output; v_sm head
// reused for pool partials.
// ---------------------------------------------------------------------------
__global__ __launch_bounds__(256, 2) void attn_kernel()
{
    const int tile = blockIdx.x;
    const int h    = blockIdx.y;
    const int b    = blockIdx.z;
    const int s0   = tile * 64;
    const int colbase = h * HD;

    extern __shared__ float sm[];
    float* q_sm = sm;                    // 64*68   (then attn weights)
    float* k_sm = q_sm + 64 * 68;        // 128*68  (then out rows)
    float* v_sm = k_sm + 128 * 68;       // 128*68  (then pool partials)

    const int tid = threadIdx.x;

    // Load Q tile
    for (int i = tid; i < 64 * 16; i += 256) {
        int row = i >> 4;
        int c4  = (i & 15) << 2;
        float4 v = *(const float4*)&g_q[((b * S_LEN) + s0 + row) * DM + colbase + c4];
        *(float4*)&q_sm[row * 68 + c4] = v;
    }
    // Load K/V window (rows s0-32 .. s0+95), zero-fill out of range
    for (int i = tid; i < 128 * 16; i += 256) {
        int row  = i >> 4;
        int c4   = (i & 15) << 2;
        int srow = s0 - 32 + row;
        float4 kv = make_float4(0.f, 0.f, 0.f, 0.f);
        float4 vv = make_float4(0.f, 0.f, 0.f, 0.f);
        if (srow >= 0 && srow < S_LEN) {
            kv = *(const float4*)&g_k[((b * S_LEN) + srow) * DM + colbase + c4];
            vv = *(const float4*)&g_v[((b * S_LEN) + srow) * DM + colbase + c4];
        }
        *(float4*)&k_sm[row * 68 + c4] = kv;
        *(float4*)&v_sm[row * 68 + c4] = vv;
    }
    __syncthreads();

    const int qg  = tid >> 3;       // 0..31 query-pair group
    const int sub = tid & 7;        // 0..7  lane within group
    const int qA  = qg * 2;         // first query of pair
    const int qB  = qA + 1;

    // ---- scores: k row r = qA + w, w = sub+8j (query A: pos w; B: pos w-1) ----
    float sA[9], sB[9];
    int ro[9];
    #pragma unroll
    for (int j = 0; j < 9; j++) {
        sA[j] = 0.f; sB[j] = 0.f;
        int w = sub + 8 * j;
        if (w > 65) w = 65;                    // clamp for address only
        ro[j] = (qA + w) * 68;
    }

    #pragma unroll
    for (int dc = 0; dc < 16; dc++) {
        float4 qa = *(const float4*)&q_sm[qA * 68 + dc * 4];
        float4 qb = *(const float4*)&q_sm[qB * 68 + dc * 4];
        #pragma unroll
        for (int j = 0; j < 9; j++) {
            float4 kv = *(const float4*)&k_sm[ro[j] + dc * 4];
            sA[j] = fmaf(qa.x, kv.x, sA[j]);
            sA[j] = fmaf(qa.y, kv.y, sA[j]);
            sA[j] = fmaf(qa.z, kv.z, sA[j]);
            sA[j] = fmaf(qa.w, kv.w, sA[j]);
            sB[j] = fmaf(qb.x, kv.x, sB[j]);
            sB[j] = fmaf(qb.y, kv.y, sB[j]);
            sB[j] = fmaf(qb.z, kv.z, sB[j]);
            sB[j] = fmaf(qb.w, kv.w, sB[j]);
        }
    }

    // masks (row validity identical for both queries: ks = s0+qA-32+w)
    #pragma unroll
    for (int j = 0; j < 9; j++) {
        int w  = sub + 8 * j;                  // original (unclamped)
        int ks = s0 + qA - 32 + w;
        bool rowok = (ks >= 0) && (ks < S_LEN);
        bool va = rowok && (w <= 64);
        bool vb = rowok && (w >= 1) && (w <= 65);
        sA[j] = va ? sA[j] * 0.125f : -1e9f;
        sB[j] = vb ? sB[j] * 0.125f : -1e9f;
    }

    // softmax per query over the 8-lane group
    float mA = -1e30f, mB = -1e30f;
    #pragma unroll
    for (int j = 0; j < 9; j++) { mA = fmaxf(mA, sA[j]); mB = fmaxf(mB, sB[j]); }
    #pragma unroll
    for (int o = 1; o <= 4; o <<= 1) {
        mA = fmaxf(mA, __shfl_xor_sync(0xffffffffu, mA, o));
        mB = fmaxf(mB, __shfl_xor_sync(0xffffffffu, mB, o));
    }
    float lA = 0.f, lB = 0.f;
    #pragma unroll
    for (int j = 0; j < 9; j++) {
        sA[j] = __expf(sA[j] - mA); lA += sA[j];
        sB[j] = __expf(sB[j] - mB); lB += sB[j];
    }
    #pragma unroll
    for (int o = 1; o <= 4; o <<= 1) {
        lA += __shfl_xor_sync(0xffffffffu, lA, o);
        lB += __shfl_xor_sync(0xffffffffu, lB, o);
    }
    const float rA = 1.0f / lA;
    const float rB = 1.0f / lB;

    // store weights (group-private q_sm rows). B stored shifted +1 so the AV
    // loop indexes both with t. Zero the unused boundary slots.
    if (sub == 0) {
        q_sm[qA * 68 + 65] = 0.f;     // A has no weight at t=65
        q_sm[qB * 68 + 0]  = 0.f;     // B has no weight at t=0
    }
    __syncwarp();
    #pragma unroll
    for (int j = 0; j < 9; j++) {
        int w = sub + 8 * j;
        if (w <= 64) q_sm[qA * 68 + w] = sA[j] * rA;
        if (w >= 1 && w <= 65) q_sm[qB * 68 + w] = sB[j] * rB;
    }

    __syncthreads();     // all k_sm score reads complete before out writes

    // ---- AV: both queries, dims d0..d0+7; v row loaded once per t ----
    const int d0 = sub * 8;
    float4 aA0 = make_float4(0.f, 0.f, 0.f, 0.f), aA1 = aA0;
    float4 aB0 = aA0, aB1 = aA0;
    const float* wAr = &q_sm[qA * 68];
    const float* wBr = &q_sm[qB * 68];
    for (int t = 0; t < 66; t++) {
        float pA = wAr[t];
        float pB = wBr[t];
        const float* vr = &v_sm[(qA + t) * 68 + d0];
        float4 v0 = *(const float4*)&vr[0];
        float4 v1 = *(const float4*)&vr[4];
        aA0.x = fmaf(pA, v0.x, aA0.x); aA0.y = fmaf(pA, v0.y, aA0.y);
        aA0.z = fmaf(pA, v0.z, aA0.z); aA0.w = fmaf(pA, v0.w, aA0.w);
        aA1.x = fmaf(pA, v1.x, aA1.x); aA1.y = fmaf(pA, v1.y, aA1.y);
        aA1.z = fmaf(pA, v1.z, aA1.z); aA1.w = fmaf(pA, v1.w, aA1.w);
        aB0.x = fmaf(pB, v0.x, aB0.x); aB0.y = fmaf(pB, v0.y, aB0.y);
        aB0.z = fmaf(pB, v0.z, aB0.z); aB0.w = fmaf(pB, v0.w, aB0.w);
        aB1.x = fmaf(pB, v1.x, aB1.x); aB1.y = fmaf(pB, v1.y, aB1.y);
        aB1.z = fmaf(pB, v1.z, aB1.z); aB1.w = fmaf(pB, v1.w, aB1.w);
    }

    // out rows -> k_sm (score reads done at the barrier above)
    *(float4*)&k_sm[qA * 68 + d0 + 0] = aA0;
    *(float4*)&k_sm[qA * 68 + d0 + 4] = aA1;
    *(float4*)&k_sm[qB * 68 + d0 + 0] = aB0;
    *(float4*)&k_sm[qB * 68 + d0 + 4] = aB1;
    __syncthreads();

    // ---- pooled partial: 4 parts x 16 rows ----
    const int d    = tid & 63;
    const int part = tid >> 6;          // 0..3
    float s = 0.f;
    #pragma unroll
    for (int r = part * 16; r < part * 16 + 16; r++)
        s += k_sm[r * 68 + d];
    v_sm[part * 64 + d] = s;
    __syncthreads();
    if (tid < 64) {
        float tot = v_sm[tid] + v_sm[64 + tid] + v_sm[128 + tid] + v_sm[192 + tid];
        g_part[((b * NTILE) + tile) * DM + h * HD + tid] = tot;
    }
}

// ---------------------------------------------------------------------------
__global__ __launch_bounds__(256) void fc_kernel(
    const float* __restrict__ Wfc, const float* __restrict__ bfc,
    float* __restrict__ out)
{
    __shared__ float pooled[DM];
    const int b   = blockIdx.y;
    const int tid = threadIdx.x;

    for (int i = tid; i < DM; i += 256) {
        float s = 0.f;
        #pragma unroll
        for (int t = 0; t < NTILE; t++)
            s += g_part[(b * NTILE + t) * DM + i];
        pooled[i] = s * (1.0f / (float)S_LEN);
    }
    __syncthreads();

    const int o = blockIdx.x * 256 + tid;
    float acc = bfc[o];
    for (int i = 0; i < DM; i++)
        acc = fmaf(pooled[i], Wfc[i * DM + o], acc);
    out[b * DM + o] = fmaxf(acc, 0.f);
}

// ---------------------------------------------------------------------------
extern "C" void kernel_launch(void* const* d_in, const int* in_sizes, int n_in,
                              void* d_out, int out_size)
{
    const float* x   = (const float*)d_in[0];
    const float* Wq  = (const float*)d_in[1];
    const float* bq  = (const float*)d_in[2];
    const float* Wk  = (const float*)d_in[3];
    const float* bk  = (const float*)d_in[4];
    const float* Wv  = (const float*)d_in[5];
    const float* bv  = (const float*)d_in[6];
    const float* Wfc = (const float*)d_in[7];
    const float* bfc = (const float*)d_in[8];
    float* out = (float*)d_out;

    // bf16 3-term split conversion
    conv_x<<<(MROWS * DM) / 256, 256>>>(x);
    conv_w<<<dim3(DM / 32, DM / 32, 3), dim3(32, 8)>>>(Wq, Wk, Wv);

    // HMMA GEMMs
    tc_gemm<<<dim3(DM / 128, MROWS / 128, 3), 256>>>(bq, bk, bv);

    // Windowed attention + per-tile pooling (87040 B dynamic smem)
    const int attn_smem = (64 + 128 + 128) * 68 * (int)sizeof(float);
    cudaFuncSetAttribute(attn_kernel,
                         cudaFuncAttributeMaxDynamicSharedMemorySize, attn_smem);
    attn_kernel<<<dim3(NTILE, NH, BATCH), 256, attn_smem>>>();

    fc_kernel<<<dim3(3, BATCH), 256>>>(Wfc, bfc, out);
}

// round 9
// speedup vs baseline: 1.9203x; 1.0344x over previous
#include <cuda_runtime.h>
#include <cuda_bf16.h>
#include <cstdint>

// Problem constants
#define S_LEN 1024
#define BATCH 2
#define DM    768
#define NH    12
#define HD    64
#define NTILE 16
#define MROWS (BATCH * S_LEN)   // 2048
#define KP    2304              // split-K' = 3*DM  (hi|lo|hi vs hi|hi|lo)
#define NCHUNK (KP / 32)        // 72

// Scratch (device globals — no allocation allowed)
__device__ float g_q[MROWS * DM];
__device__ float g_k[MROWS * DM];
__device__ float g_v[MROWS * DM];
__device__ float g_part[BATCH * NTILE * DM];
__device__ __nv_bfloat16 g_ahl[MROWS * KP];        // A' = [hi | lo | hi]
__device__ __nv_bfloat16 g_wt[3 * DM * KP];        // W'^T = [hi | hi | lo], [n][k']

// ---------------- PTX helpers (portable: ldmatrix + mma.sync) ----------------
__device__ __forceinline__ uint32_t smem_u32(const void* p) {
    uint32_t a;
    asm("{ .reg .u64 t; cvta.to.shared.u64 t, %1; cvt.u32.u64 %0, t; }"
        : "=r"(a) : "l"(p));
    return a;
}
__device__ __forceinline__ void ldsm_x4(uint32_t& r0, uint32_t& r1,
                                        uint32_t& r2, uint32_t& r3, uint32_t addr) {
    asm volatile("ldmatrix.sync.aligned.m8n8.x4.shared.b16 {%0,%1,%2,%3}, [%4];"
                 : "=r"(r0), "=r"(r1), "=r"(r2), "=r"(r3) : "r"(addr));
}
__device__ __forceinline__ void mma16816(float* c, uint32_t a0, uint32_t a1,
                                         uint32_t a2, uint32_t a3,
                                         uint32_t b0, uint32_t b1) {
    asm volatile("mma.sync.aligned.m16n8k16.row.col.f32.bf16.bf16.f32 "
                 "{%0,%1,%2,%3}, {%4,%5,%6,%7}, {%8,%9}, {%0,%1,%2,%3};"
                 : "+f"(c[0]), "+f"(c[1]), "+f"(c[2]), "+f"(c[3])
                 : "r"(a0), "r"(a1), "r"(a2), "r"(a3), "r"(b0), "r"(b1));
}

// ---------------------------------------------------------------------------
// Convert x -> A' = [hi | lo | hi] along K'
// ---------------------------------------------------------------------------
__global__ __launch_bounds__(256) void conv_x(const float* __restrict__ x)
{
    int i = blockIdx.x * 256 + threadIdx.x;
    float a = x[i];
    __nv_bfloat16 hi = __float2bfloat16(a);
    __nv_bfloat16 lo = __float2bfloat16(a - __bfloat162float(hi));
    int m = i / DM;
    int k = i - m * DM;
    __nv_bfloat16* row = g_ahl + (size_t)m * KP;
    row[k]            = hi;
    row[DM + k]       = lo;
    row[2 * DM + k]   = hi;
}

// ---------------------------------------------------------------------------
// Convert + transpose W[k][n] -> Wt[n] = [hi | hi | lo] along K' (per z)
// ---------------------------------------------------------------------------
__global__ __launch_bounds__(256) void conv_w(
    const float* __restrict__ Wq, const float* __restrict__ Wk,
    const float* __restrict__ Wv)
{
    __shared__ float tile[32][33];
    const int z  = blockIdx.z;
    const float* W = (z == 0) ? Wq : (z == 1) ? Wk : Wv;
    __nv_bfloat16* out = g_wt + (size_t)z * DM * KP;
    const int k0 = blockIdx.x * 32;
    const int n0 = blockIdx.y * 32;
    const int tx = threadIdx.x;
    const int ty = threadIdx.y;

    #pragma unroll
    for (int r = ty; r < 32; r += 8)
        tile[r][tx] = W[(k0 + r) * DM + n0 + tx];
    __syncthreads();
    #pragma unroll
    for (int r = ty; r < 32; r += 8) {
        float v = tile[tx][r];
        __nv_bfloat16 hi = __float2bfloat16(v);
        __nv_bfloat16 lo = __float2bfloat16(v - __bfloat162float(hi));
        __nv_bfloat16* row = out + (size_t)(n0 + r) * KP;
        row[k0 + tx]            = hi;
        row[DM + k0 + tx]       = hi;
        row[2 * DM + k0 + tx]   = lo;
    }
}

// ---------------------------------------------------------------------------
// bf16 HMMA GEMM: C[2048x768] = A'[2048x2304] @ Wt^T + bias, per z.
// ---------------------------------------------------------------------------
#define LDA 40

__global__ __launch_bounds__(256, 2) void tc_gemm(
    const float* __restrict__ bq, const float* __restrict__ bk,
    const float* __restrict__ bv)
{
    __shared__ __nv_bfloat16 As[2][128 * LDA];
    __shared__ __nv_bfloat16 Bs[2][128 * LDA];

    const int tid  = threadIdx.x;
    const int warp = tid >> 5;
    const int lane = tid & 31;
    const int wm = warp >> 2;
    const int wn = warp & 3;

    const int z  = blockIdx.z;
    const int n0 = blockIdx.x * 128;
    const int m0 = blockIdx.y * 128;
    const float* bias = (z == 0) ? bq : (z == 1) ? bk : bv;
    float* C = (z == 0) ? g_q : (z == 1) ? g_k : g_v;
    const __nv_bfloat16* Wt = g_wt + (size_t)z * DM * KP;

    const int f0   = tid;
    const int row0 = f0 >> 2,  q0 = f0 & 3;
    const int row1 = (f0 + 256) >> 2, q1 = (f0 + 256) & 3;

    const __nv_bfloat16* Ag = g_ahl + (size_t)m0 * KP;
    const __nv_bfloat16* Bg = Wt    + (size_t)n0 * KP;

    const int a_r = lane & 15, a_c = (lane >> 4) * 8;
    const int b_n = (lane & 7) + ((lane >> 4) << 3);
    const int b_k = ((lane >> 3) & 1) * 8;

    const uint32_t asm_base = smem_u32(&As[0][0]);
    const uint32_t bsm_base = smem_u32(&Bs[0][0]);
    const uint32_t buf_bytes = 128 * LDA * 2;

    float acc[4][4][4];
    #pragma unroll
    for (int i = 0; i < 4; i++)
        #pragma unroll
        for (int j = 0; j < 4; j++)
            #pragma unroll
            for (int r = 0; r < 4; r++) acc[i][j][r] = 0.0f;

    {
        *(float4*)&As[0][row0 * LDA + q0 * 8] = *(const float4*)(Ag + (size_t)row0 * KP + q0 * 8);
        *(float4*)&As[0][row1 * LDA + q1 * 8] = *(const float4*)(Ag + (size_t)row1 * KP + q1 * 8);
        *(float4*)&Bs[0][row0 * LDA + q0 * 8] = *(const float4*)(Bg + (size_t)row0 * KP + q0 * 8);
        *(float4*)&Bs[0][row1 * LDA + q1 * 8] = *(const float4*)(Bg + (size_t)row1 * KP + q1 * 8);
    }
    __syncthreads();

    int buf = 0;
    for (int c = 0; c < NCHUNK; c++) {
        const bool has_next = (c + 1) < NCHUNK;
        float4 pA0, pA1, pB0, pB1;
        if (has_next) {
            const size_t ko = (size_t)(c + 1) * 32;
            pA0 = *(const float4*)(Ag + (size_t)row0 * KP + ko + q0 * 8);
            pA1 = *(const float4*)(Ag + (size_t)row1 * KP + ko + q1 * 8);
            pB0 = *(const float4*)(Bg + (size_t)row0 * KP + ko + q0 * 8);
            pB1 = *(const float4*)(Bg + (size_t)row1 * KP + ko + q1 * 8);
        }

        const uint32_t ab = asm_base + buf * buf_bytes;
        const uint32_t bb = bsm_base + buf * buf_bytes;
        #pragma unroll
        for (int ks = 0; ks < 2; ks++) {
            const int k0 = ks * 16;
            uint32_t a[4][4];
            #pragma unroll
            for (int mt = 0; mt < 4; mt++) {
                uint32_t addr = ab + ((wm * 64 + mt * 16 + a_r) * LDA + k0 + a_c) * 2;
                ldsm_x4(a[mt][0], a[mt][1], a[mt][2], a[mt][3], addr);
            }
            uint32_t b[2][4];
            #pragma unroll
            for (int np = 0; np < 2; np++) {
                uint32_t addr = bb + ((wn * 32 + np * 16 + b_n) * LDA + k0 + b_k) * 2;
                ldsm_x4(b[np][0], b[np][1], b[np][2], b[np][3], addr);
            }
            #pragma unroll
            for (int mt = 0; mt < 4; mt++)
                #pragma unroll
                for (int nt = 0; nt < 4; nt++)
                    mma16816(acc[mt][nt],
                             a[mt][0], a[mt][1], a[mt][2], a[mt][3],
                             b[nt >> 1][(nt & 1) * 2], b[nt >> 1][(nt & 1) * 2 + 1]);
        }

        if (has_next) {
            const int nb = buf ^ 1;
            *(float4*)&As[nb][row0 * LDA + q0 * 8] = pA0;
            *(float4*)&As[nb][row1 * LDA + q1 * 8] = pA1;
            *(float4*)&Bs[nb][row0 * LDA + q0 * 8] = pB0;
            *(float4*)&Bs[nb][row1 * LDA + q1 * 8] = pB1;
            __syncthreads();
            buf = nb;
        }
    }

    const int g  = lane >> 2;
    const int tg = lane & 3;
    #pragma unroll
    for (int mt = 0; mt < 4; mt++) {
        const int row = m0 + wm * 64 + mt * 16 + g;
        float* Crow0 = C + (size_t)row * DM;
        float* Crow1 = C + (size_t)(row + 8) * DM;
        #pragma unroll
        for (int nt = 0; nt < 4; nt++) {
            const int col = n0 + wn * 32 + nt * 8 + tg * 2;
            const float bx = __ldg(&bias[col]);
            const float by = __ldg(&bias[col + 1]);
            float2 v0 = make_float2(acc[mt][nt][0] + bx, acc[mt][nt][1] + by);
            float2 v1 = make_float2(acc[mt][nt][2] + bx, acc[mt][nt][3] + by);
            *(float2*)&Crow0[col] = v0;
            *(float2*)&Crow1[col] = v1;
        }
    }
}

// ---------------------------------------------------------------------------
// Windowed attention, v4: 256 threads; 16-lane group owns FOUR adjacent
// queries. Scores indexed by k-row: lane sub owns rows qA+sub+16j (j=0..4),
// computing 4 dots per row (query c at window w=row-qA-c). Weight of query c
// for row r lands at slot r-qA of weight-row c -> slots 0..67 covered exactly
// once, branch-free float4 AV. Halves per-query smem traffic vs v3.
// ---------------------------------------------------------------------------
__global__ __launch_bounds__(256, 2) void attn_kernel()
{
    const int tile = blockIdx.x;
    const int h    = blockIdx.y;
    const int b    = blockIdx.z;
    const int s0   = tile * 64;
    const int colbase = h * HD;

    extern __shared__ float sm[];
    float* q_sm = sm;                    // 64*68   (then attn weights)
    float* k_sm = q_sm + 64 * 68;        // 128*68  (then out rows)
    float* v_sm = k_sm + 128 * 68;       // 128*68  (then pool partials)

    const int tid = threadIdx.x;

    // Load Q tile
    for (int i = tid; i < 64 * 16; i += 256) {
        int row = i >> 4;
        int c4  = (i & 15) << 2;
        float4 v = *(const float4*)&g_q[((b * S_LEN) + s0 + row) * DM + colbase + c4];
        *(float4*)&q_sm[row * 68 + c4] = v;
    }
    // Load K/V window (rows s0-32 .. s0+95), zero-fill out of range
    for (int i = tid; i < 128 * 16; i += 256) {
        int row  = i >> 4;
        int c4   = (i & 15) << 2;
        int srow = s0 - 32 + row;
        float4 kv = make_float4(0.f, 0.f, 0.f, 0.f);
        float4 vv = make_float4(0.f, 0.f, 0.f, 0.f);
        if (srow >= 0 && srow < S_LEN) {
            kv = *(const float4*)&g_k[((b * S_LEN) + srow) * DM + colbase + c4];
            vv = *(const float4*)&g_v[((b * S_LEN) + srow) * DM + colbase + c4];
        }
        *(float4*)&k_sm[row * 68 + c4] = kv;
        *(float4*)&v_sm[row * 68 + c4] = vv;
    }
    __syncthreads();

    const int grp = tid >> 4;       // 0..15 query-quad group
    const int sub = tid & 15;       // 0..15 lane within group
    const int qA  = grp * 4;        // first query of quad

    // ---- scores, indexed by k-row: lane owns rows rsm = qA+sub+16j ----
    int ro[5];
    #pragma unroll
    for (int j = 0; j < 5; j++) {
        int rsm = qA + sub + 16 * j;
        if (rsm > 127) rsm = 127;       // address clamp; masked below
        ro[j] = rsm * 68;
    }

    float sc[5][4];
    #pragma unroll
    for (int j = 0; j < 5; j++)
        #pragma unroll
        for (int c = 0; c < 4; c++) sc[j][c] = 0.f;

    #pragma unroll
    for (int dc = 0; dc < 16; dc++) {
        float4 qv[4];
        #pragma unroll
        for (int c = 0; c < 4; c++)
            qv[c] = *(const float4*)&q_sm[(qA + c) * 68 + dc * 4];
        #pragma unroll
        for (int j = 0; j < 5; j++) {
            float4 kv = *(const float4*)&k_sm[ro[j] + dc * 4];
            #pragma unroll
            for (int c = 0; c < 4; c++) {
                sc[j][c] = fmaf(qv[c].x, kv.x, sc[j][c]);
                sc[j][c] = fmaf(qv[c].y, kv.y, sc[j][c]);
                sc[j][c] = fmaf(qv[c].z, kv.z, sc[j][c]);
                sc[j][c] = fmaf(qv[c].w, kv.w, sc[j][c]);
            }
        }
    }

    // masks: row rsm valid if global k-row in range; query c valid if w in [0,64]
    #pragma unroll
    for (int j = 0; j < 5; j++) {
        int rsm = qA + sub + 16 * j;            // unclamped
        int gk  = s0 + rsm - 32;
        bool rowok = (rsm <= 127) && (gk >= 0) && (gk < S_LEN);
        #pragma unroll
        for (int c = 0; c < 4; c++) {
            int w = sub + 16 * j - c;
            bool ok = rowok && (w >= 0) && (w <= 64);
            sc[j][c] = ok ? sc[j][c] * 0.125f : -1e9f;
        }
    }

    // softmax per query over 16-lane group
    float mx[4], lsum[4];
    #pragma unroll
    for (int c = 0; c < 4; c++) {
        float m = -1e30f;
        #pragma unroll
        for (int j = 0; j < 5; j++) m = fmaxf(m, sc[j][c]);
        #pragma unroll
        for (int o = 1; o <= 8; o <<= 1)
            m = fmaxf(m, __shfl_xor_sync(0xffffffffu, m, o, 16));
        mx[c] = m;
    }
    #pragma unroll
    for (int c = 0; c < 4; c++) {
        float l = 0.f;
        #pragma unroll
        for (int j = 0; j < 5; j++) { sc[j][c] = __expf(sc[j][c] - mx[c]); l += sc[j][c]; }
        #pragma unroll
        for (int o = 1; o <= 8; o <<= 1)
            l += __shfl_xor_sync(0xffffffffu, l, o, 16);
        lsum[c] = 1.0f / l;
    }

    // store weights: slot = rsm - qA = sub + 16j (< 68); invalid entries are 0
    #pragma unroll
    for (int j = 0; j < 5; j++) {
        int slot = sub + 16 * j;
        if (slot < 68) {
            #pragma unroll
            for (int c = 0; c < 4; c++)
                q_sm[(qA + c) * 68 + slot] = sc[j][c] * lsum[c];
        }
    }
    __syncwarp();

    // ---- AV: lane owns dims sub*4..sub*4+3 for all 4 queries ----
    const int d0 = sub * 4;
    float4 acc[4];
    #pragma unroll
    for (int c = 0; c < 4; c++) acc[c] = make_float4(0.f, 0.f, 0.f, 0.f);

    #pragma unroll
    for (int tb = 0; tb < 17; tb++) {
        float4 wv[4];
        #pragma unroll
        for (int c = 0; c < 4; c++)
            wv[c] = *(const float4*)&q_sm[(qA + c) * 68 + tb * 4];
        #pragma unroll
        for (int s = 0; s < 4; s++) {
            int t = tb * 4 + s;
            float4 v4 = *(const float4*)&v_sm[(qA + t) * 68 + d0];
            float w0 = (s == 0) ? wv[0].x : (s == 1) ? wv[0].y : (s == 2) ? wv[0].z : wv[0].w;
            float w1 = (s == 0) ? wv[1].x : (s == 1) ? wv[1].y : (s == 2) ? wv[1].z : wv[1].w;
            float w2 = (s == 0) ? wv[2].x : (s == 1) ? wv[2].y : (s == 2) ? wv[2].z : wv[2].w;
            float w3 = (s == 0) ? wv[3].x : (s == 1) ? wv[3].y : (s == 2) ? wv[3].z : wv[3].w;
            acc[0].x = fmaf(w0, v4.x, acc[0].x); acc[0].y = fmaf(w0, v4.y, acc[0].y);
            acc[0].z = fmaf(w0, v4.z, acc[0].z); acc[0].w = fmaf(w0, v4.w, acc[0].w);
            acc[1].x = fmaf(w1, v4.x, acc[1].x); acc[1].y = fmaf(w1, v4.y, acc[1].y);
            acc[1].z = fmaf(w1, v4.z, acc[1].z); acc[1].w = fmaf(w1, v4.w, acc[1].w);
            acc[2].x = fmaf(w2, v4.x, acc[2].x); acc[2].y = fmaf(w2, v4.y, acc[2].y);
            acc[2].z = fmaf(w2, v4.z, acc[2].z); acc[2].w = fmaf(w2, v4.w, acc[2].w);
            acc[3].x = fmaf(w3, v4.x, acc[3].x); acc[3].y = fmaf(w3, v4.y, acc[3].y);
            acc[3].z = fmaf(w3, v4.z, acc[3].z); acc[3].w = fmaf(w3, v4.w, acc[3].w);
        }
    }

    __syncthreads();     // all k_sm/v_sm/q_sm reads complete
    #pragma unroll
    for (int c = 0; c < 4; c++)
        *(float4*)&k_sm[(qA + c) * 68 + d0] = acc[c];
    __syncthreads();

    // ---- pooled partial: 4 parts x 16 rows ----
    const int d    = tid & 63;
    const int part = tid >> 6;          // 0..3
    float s = 0.f;
    #pragma unroll
    for (int r = part * 16; r < part * 16 + 16; r++)
        s += k_sm[r * 68 + d];
    v_sm[part * 64 + d] = s;
    __syncthreads();
    if (tid < 64) {
        float tot = v_sm[tid] + v_sm[64 + tid] + v_sm[128 + tid] + v_sm[192 + tid];
        g_part[((b * NTILE) + tile) * DM + h * HD + tid] = tot;
    }
}

// ---------------------------------------------------------------------------
__global__ __launch_bounds__(256) void fc_kernel(
    const float* __restrict__ Wfc, const float* __restrict__ bfc,
    float* __restrict__ out)
{
    __shared__ float pooled[DM];
    const int b   = blockIdx.y;
    const int tid = threadIdx.x;

    for (int i = tid; i < DM; i += 256) {
        float s = 0.f;
        #pragma unroll
        for (int t = 0; t < NTILE; t++)
            s += g_part[(b * NTILE + t) * DM + i];
        pooled[i] = s * (1.0f / (float)S_LEN);
    }
    __syncthreads();

    const int o = blockIdx.x * 256 + tid;
    float acc = bfc[o];
    for (int i = 0; i < DM; i++)
        acc = fmaf(pooled[i], Wfc[i * DM + o], acc);
    out[b * DM + o] = fmaxf(acc, 0.f);
}

// ---------------------------------------------------------------------------
extern "C" void kernel_launch(void* const* d_in, const int* in_sizes, int n_in,
                              void* d_out, int out_size)
{
    const float* x   = (const float*)d_in[0];
    const float* Wq  = (const float*)d_in[1];
    const float* bq  = (const float*)d_in[2];
    const float* Wk  = (const float*)d_in[3];
    const float* bk  = (const float*)d_in[4];
    const float* Wv  = (const float*)d_in[5];
    const float* bv  = (const float*)d_in[6];
    const float* Wfc = (const float*)d_in[7];
    const float* bfc = (const float*)d_in[8];
    float* out = (float*)d_out;

    // bf16 3-term split conversion
    conv_x<<<(MROWS * DM) / 256, 256>>>(x);
    conv_w<<<dim3(DM / 32, DM / 32, 3), dim3(32, 8)>>>(Wq, Wk, Wv);

    // HMMA GEMMs
    tc_gemm<<<dim3(DM / 128, MROWS / 128, 3), 256>>>(bq, bk, bv);

    // Windowed attention + per-tile pooling (87040 B dynamic smem)
    const int attn_smem = (64 + 128 + 128) * 68 * (int)sizeof(float);
    cudaFuncSetAttribute(attn_kernel,
                         cudaFuncAttributeMaxDynamicSharedMemorySize, attn_smem);
    attn_kernel<<<dim3(NTILE, NH, BATCH), 256, attn_smem>>>();

    fc_kernel<<<dim3(3, BATCH), 256>>>(Wfc, bfc, out);
}

// round 10
// speedup vs baseline: 2.3542x; 1.2260x over previous
#include <cuda_runtime.h>
#include <cuda_fp16.h>
#include <cstdint>

// Problem constants
#define S_LEN 1024
#define BATCH 2
#define DM    768
#define NH    12
#define HD    64
#define NTILE 16
#define MROWS (BATCH * S_LEN)   // 2048
#define KP    1536              // fp16 2-term split: A'=[hi|lo], W'=[hi|hi]
#define NCHUNK (KP / 32)        // 48

// Scratch (device globals — no allocation allowed)
__device__ float g_q[MROWS * DM];
__device__ float g_k[MROWS * DM];
__device__ float g_v[MROWS * DM];
__device__ float g_part[BATCH * NTILE * DM];
__device__ __half g_ahl[MROWS * KP];        // A' = [hi(x) | lo(x)]
__device__ __half g_wt[3 * DM * KP];        // W'^T = [hi | hi], [n][k'] K-major

// ---------------- PTX helpers (portable: ldmatrix + mma.sync) ----------------
__device__ __forceinline__ uint32_t smem_u32(const void* p) {
    uint32_t a;
    asm("{ .reg .u64 t; cvta.to.shared.u64 t, %1; cvt.u32.u64 %0, t; }"
        : "=r"(a) : "l"(p));
    return a;
}
__device__ __forceinline__ void ldsm_x4(uint32_t& r0, uint32_t& r1,
                                        uint32_t& r2, uint32_t& r3, uint32_t addr) {
    asm volatile("ldmatrix.sync.aligned.m8n8.x4.shared.b16 {%0,%1,%2,%3}, [%4];"
                 : "=r"(r0), "=r"(r1), "=r"(r2), "=r"(r3) : "r"(addr));
}
__device__ __forceinline__ void mma16816(float* c, uint32_t a0, uint32_t a1,
                                         uint32_t a2, uint32_t a3,
                                         uint32_t b0, uint32_t b1) {
    asm volatile("mma.sync.aligned.m16n8k16.row.col.f32.f16.f16.f32 "
                 "{%0,%1,%2,%3}, {%4,%5,%6,%7}, {%8,%9}, {%0,%1,%2,%3};"
                 : "+f"(c[0]), "+f"(c[1]), "+f"(c[2]), "+f"(c[3])
                 : "r"(a0), "r"(a1), "r"(a2), "r"(a3), "r"(b0), "r"(b1));
}

// ---------------------------------------------------------------------------
// Convert x -> A' = [hi | lo] along K'  (fp16 split: hi+lo == x to fp32-ish)
// ---------------------------------------------------------------------------
__global__ __launch_bounds__(256) void conv_x(const float* __restrict__ x)
{
    int i = blockIdx.x * 256 + threadIdx.x;
    float a = x[i];
    __half hi = __float2half_rn(a);
    __half lo = __float2half_rn(a - __half2float(hi));
    int m = i / DM;
    int k = i - m * DM;
    __half* row = g_ahl + (size_t)m * KP;
    row[k]      = hi;
    row[DM + k] = lo;
}

// ---------------------------------------------------------------------------
// Convert + transpose W[k][n] -> Wt[n] = [hi | hi] along K' (per z)
// ---------------------------------------------------------------------------
__global__ __launch_bounds__(256) void conv_w(
    const float* __restrict__ Wq, const float* __restrict__ Wk,
    const float* __restrict__ Wv)
{
    __shared__ float tile[32][33];
    const int z  = blockIdx.z;
    const float* W = (z == 0) ? Wq : (z == 1) ? Wk : Wv;
    __half* out = g_wt + (size_t)z * DM * KP;
    const int k0 = blockIdx.x * 32;
    const int n0 = blockIdx.y * 32;
    const int tx = threadIdx.x;
    const int ty = threadIdx.y;

    #pragma unroll
    for (int r = ty; r < 32; r += 8)
        tile[r][tx] = W[(k0 + r) * DM + n0 + tx];
    __syncthreads();
    #pragma unroll
    for (int r = ty; r < 32; r += 8) {
        float v = tile[tx][r];
        __half hi = __float2half_rn(v);
        __half* row = out + (size_t)(n0 + r) * KP;
        row[k0 + tx]      = hi;
        row[DM + k0 + tx] = hi;
    }
}

// ---------------------------------------------------------------------------
// fp16 HMMA GEMM: C[2048x768] = A'[2048x1536] @ Wt^T + bias, per z.
// CTA 128x128, BK=32, 8 warps (2x4), warp tile 64x32, mma.sync m16n8k16.
// ---------------------------------------------------------------------------
#define LDA 40

__global__ __launch_bounds__(256, 2) void tc_gemm(
    const float* __restrict__ bq, const float* __restrict__ bk,
    const float* __restrict__ bv)
{
    __shared__ __half As[2][128 * LDA];
    __shared__ __half Bs[2][128 * LDA];

    const int tid  = threadIdx.x;
    const int warp = tid >> 5;
    const int lane = tid & 31;
    const int wm = warp >> 2;
    const int wn = warp & 3;

    const int z  = blockIdx.z;
    const int n0 = blockIdx.x * 128;
    const int m0 = blockIdx.y * 128;
    const float* bias = (z == 0) ? bq : (z == 1) ? bk : bv;
    float* C = (z == 0) ? g_q : (z == 1) ? g_k : g_v;
    const __half* Wt = g_wt + (size_t)z * DM * KP;

    const int f0   = tid;
    const int row0 = f0 >> 2,  q0 = f0 & 3;
    const int row1 = (f0 + 256) >> 2, q1 = (f0 + 256) & 3;

    const __half* Ag = g_ahl + (size_t)m0 * KP;
    const __half* Bg = Wt    + (size_t)n0 * KP;

    const int a_r = lane & 15, a_c = (lane >> 4) * 8;
    const int b_n = (lane & 7) + ((lane >> 4) << 3);
    const int b_k = ((lane >> 3) & 1) * 8;

    const uint32_t asm_base = smem_u32(&As[0][0]);
    const uint32_t bsm_base = smem_u32(&Bs[0][0]);
    const uint32_t buf_bytes = 128 * LDA * 2;

    float acc[4][4][4];
    #pragma unroll
    for (int i = 0; i < 4; i++)
        #pragma unroll
        for (int j = 0; j < 4; j++)
            #pragma unroll
            for (int r = 0; r < 4; r++) acc[i][j][r] = 0.0f;

    {
        *(float4*)&As[0][row0 * LDA + q0 * 8] = *(const float4*)(Ag + (size_t)row0 * KP + q0 * 8);
        *(float4*)&As[0][row1 * LDA + q1 * 8] = *(const float4*)(Ag + (size_t)row1 * KP + q1 * 8);
        *(float4*)&Bs[0][row0 * LDA + q0 * 8] = *(const float4*)(Bg + (size_t)row0 * KP + q0 * 8);
        *(float4*)&Bs[0][row1 * LDA + q1 * 8] = *(const float4*)(Bg + (size_t)row1 * KP + q1 * 8);
    }
    __syncthreads();

    int buf = 0;
    for (int c = 0; c < NCHUNK; c++) {
        const bool has_next = (c + 1) < NCHUNK;
        float4 pA0, pA1, pB0, pB1;
        if (has_next) {
            const size_t ko = (size_t)(c + 1) * 32;
            pA0 = *(const float4*)(Ag + (size_t)row0 * KP + ko + q0 * 8);
            pA1 = *(const float4*)(Ag + (size_t)row1 * KP + ko + q1 * 8);
            pB0 = *(const float4*)(Bg + (size_t)row0 * KP + ko + q0 * 8);
            pB1 = *(const float4*)(Bg + (size_t)row1 * KP + ko + q1 * 8);
        }

        const uint32_t ab = asm_base + buf * buf_bytes;
        const uint32_t bb = bsm_base + buf * buf_bytes;
        #pragma unroll
        for (int ks = 0; ks < 2; ks++) {
            const int k0 = ks * 16;
            uint32_t a[4][4];
            #pragma unroll
            for (int mt = 0; mt < 4; mt++) {
                uint32_t addr = ab + ((wm * 64 + mt * 16 + a_r) * LDA + k0 + a_c) * 2;
                ldsm_x4(a[mt][0], a[mt][1], a[mt][2], a[mt][3], addr);
            }
            uint32_t b[2][4];
            #pragma unroll
            for (int np = 0; np < 2; np++) {
                uint32_t addr = bb + ((wn * 32 + np * 16 + b_n) * LDA + k0 + b_k) * 2;
                ldsm_x4(b[np][0], b[np][1], b[np][2], b[np][3], addr);
            }
            #pragma unroll
            for (int mt = 0; mt < 4; mt++)
                #pragma unroll
                for (int nt = 0; nt < 4; nt++)
                    mma16816(acc[mt][nt],
                             a[mt][0], a[mt][1], a[mt][2], a[mt][3],
                             b[nt >> 1][(nt & 1) * 2], b[nt >> 1][(nt & 1) * 2 + 1]);
        }

        if (has_next) {
            const int nb = buf ^ 1;
            *(float4*)&As[nb][row0 * LDA + q0 * 8] = pA0;
            *(float4*)&As[nb][row1 * LDA + q1 * 8] = pA1;
            *(float4*)&Bs[nb][row0 * LDA + q0 * 8] = pB0;
            *(float4*)&Bs[nb][row1 * LDA + q1 * 8] = pB1;
            __syncthreads();
            buf = nb;
        }
    }

    const int g  = lane >> 2;
    const int tg = lane & 3;
    #pragma unroll
    for (int mt = 0; mt < 4; mt++) {
        const int row = m0 + wm * 64 + mt * 16 + g;
        float* Crow0 = C + (size_t)row * DM;
        float* Crow1 = C + (size_t)(row + 8) * DM;
        #pragma unroll
        for (int nt = 0; nt < 4; nt++) {
            const int col = n0 + wn * 32 + nt * 8 + tg * 2;
            const float bx = __ldg(&bias[col]);
            const float by = __ldg(&bias[col + 1]);
            float2 v0 = make_float2(acc[mt][nt][0] + bx, acc[mt][nt][1] + by);
            float2 v1 = make_float2(acc[mt][nt][2] + bx, acc[mt][nt][3] + by);
            *(float2*)&Crow0[col] = v0;
            *(float2*)&Crow1[col] = v1;
        }
    }
}

// ---------------------------------------------------------------------------
// Windowed attention, v4 (unchanged from R9): 16-lane group owns 4 queries,
// scores indexed by k-row, branch-free float4 AV.
// ---------------------------------------------------------------------------
__global__ __launch_bounds__(256, 2) void attn_kernel()
{
    const int tile = blockIdx.x;
    const int h    = blockIdx.y;
    const int b    = blockIdx.z;
    const int s0   = tile * 64;
    const int colbase = h * HD;

    extern __shared__ float sm[];
    float* q_sm = sm;                    // 64*68   (then attn weights)
    float* k_sm = q_sm + 64 * 68;        // 128*68  (then out rows)
    float* v_sm = k_sm + 128 * 68;       // 128*68  (then pool partials)

    const int tid = threadIdx.x;

    for (int i = tid; i < 64 * 16; i += 256) {
        int row = i >> 4;
        int c4  = (i & 15) << 2;
        float4 v = *(const float4*)&g_q[((b * S_LEN) + s0 + row) * DM + colbase + c4];
        *(float4*)&q_sm[row * 68 + c4] = v;
    }
    for (int i = tid; i < 128 * 16; i += 256) {
        int row  = i >> 4;
        int c4   = (i & 15) << 2;
        int srow = s0 - 32 + row;
        float4 kv = make_float4(0.f, 0.f, 0.f, 0.f);
        float4 vv = make_float4(0.f, 0.f, 0.f, 0.f);
        if (srow >= 0 && srow < S_LEN) {
            kv = *(const float4*)&g_k[((b * S_LEN) + srow) * DM + colbase + c4];
            vv = *(const float4*)&g_v[((b * S_LEN) + srow) * DM + colbase + c4];
        }
        *(float4*)&k_sm[row * 68 + c4] = kv;
        *(float4*)&v_sm[row * 68 + c4] = vv;
    }
    __syncthreads();

    const int grp = tid >> 4;
    const int sub = tid & 15;
    const int qA  = grp * 4;

    int ro[5];
    #pragma unroll
    for (int j = 0; j < 5; j++) {
        int rsm = qA + sub + 16 * j;
        if (rsm > 127) rsm = 127;
        ro[j] = rsm * 68;
    }

    float sc[5][4];
    #pragma unroll
    for (int j = 0; j < 5; j++)
        #pragma unroll
        for (int c = 0; c < 4; c++) sc[j][c] = 0.f;

    #pragma unroll
    for (int dc = 0; dc < 16; dc++) {
        float4 qv[4];
        #pragma unroll
        for (int c = 0; c < 4; c++)
            qv[c] = *(const float4*)&q_sm[(qA + c) * 68 + dc * 4];
        #pragma unroll
        for (int j = 0; j < 5; j++) {
            float4 kv = *(const float4*)&k_sm[ro[j] + dc * 4];
            #pragma unroll
            for (int c = 0; c < 4; c++) {
                sc[j][c] = fmaf(qv[c].x, kv.x, sc[j][c]);
                sc[j][c] = fmaf(qv[c].y, kv.y, sc[j][c]);
                sc[j][c] = fmaf(qv[c].z, kv.z, sc[j][c]);
                sc[j][c] = fmaf(qv[c].w, kv.w, sc[j][c]);
            }
        }
    }

    #pragma unroll
    for (int j = 0; j < 5; j++) {
        int rsm = qA + sub + 16 * j;
        int gk  = s0 + rsm - 32;
        bool rowok = (rsm <= 127) && (gk >= 0) && (gk < S_LEN);
        #pragma unroll
        for (int c = 0; c < 4; c++) {
            int w = sub + 16 * j - c;
            bool ok = rowok && (w >= 0) && (w <= 64);
            sc[j][c] = ok ? sc[j][c] * 0.125f : -1e9f;
        }
    }

    float mx[4], lsum[4];
    #pragma unroll
    for (int c = 0; c < 4; c++) {
        float m = -1e30f;
        #pragma unroll
        for (int j = 0; j < 5; j++) m = fmaxf(m, sc[j][c]);
        #pragma unroll
        for (int o = 1; o <= 8; o <<= 1)
            m = fmaxf(m, __shfl_xor_sync(0xffffffffu, m, o, 16));
        mx[c] = m;
    }
    #pragma unroll
    for (int c = 0; c < 4; c++) {
        float l = 0.f;
        #pragma unroll
        for (int j = 0; j < 5; j++) { sc[j][c] = __expf(sc[j][c] - mx[c]); l += sc[j][c]; }
        #pragma unroll
        for (int o = 1; o <= 8; o <<= 1)
            l += __shfl_xor_sync(0xffffffffu, l, o, 16);
        lsum[c] = 1.0f / l;
    }

    #pragma unroll
    for (int j = 0; j < 5; j++) {
        int slot = sub + 16 * j;
        if (slot < 68) {
            #pragma unroll
            for (int c = 0; c < 4; c++)
                q_sm[(qA + c) * 68 + slot] = sc[j][c] * lsum[c];
        }
    }
    __syncwarp();

    const int d0 = sub * 4;
    float4 acc[4];
    #pragma unroll
    for (int c = 0; c < 4; c++) acc[c] = make_float4(0.f, 0.f, 0.f, 0.f);

    #pragma unroll
    for (int tb = 0; tb < 17; tb++) {
        float4 wv[4];
        #pragma unroll
        for (int c = 0; c < 4; c++)
            wv[c] = *(const float4*)&q_sm[(qA + c) * 68 + tb * 4];
        #pragma unroll
        for (int s = 0; s < 4; s++) {
            int t = tb * 4 + s;
            float4 v4 = *(const float4*)&v_sm[(qA + t) * 68 + d0];
            float w0 = (s == 0) ? wv[0].x : (s == 1) ? wv[0].y : (s == 2) ? wv[0].z : wv[0].w;
            float w1 = (s == 0) ? wv[1].x : (s == 1) ? wv[1].y : (s == 2) ? wv[1].z : wv[1].w;
            float w2 = (s == 0) ? wv[2].x : (s == 1) ? wv[2].y : (s == 2) ? wv[2].z : wv[2].w;
            float w3 = (s == 0) ? wv[3].x : (s == 1) ? wv[3].y : (s == 2) ? wv[3].z : wv[3].w;
            acc[0].x = fmaf(w0, v4.x, acc[0].x); acc[0].y = fmaf(w0, v4.y, acc[0].y);
            acc[0].z = fmaf(w0, v4.z, acc[0].z); acc[0].w = fmaf(w0, v4.w, acc[0].w);
            acc[1].x = fmaf(w1, v4.x, acc[1].x); acc[1].y = fmaf(w1, v4.y, acc[1].y);
            acc[1].z = fmaf(w1, v4.z, acc[1].z); acc[1].w = fmaf(w1, v4.w, acc[1].w);
            acc[2].x = fmaf(w2, v4.x, acc[2].x); acc[2].y = fmaf(w2, v4.y, acc[2].y);
            acc[2].z = fmaf(w2, v4.z, acc[2].z); acc[2].w = fmaf(w2, v4.w, acc[2].w);
            acc[3].x = fmaf(w3, v4.x, acc[3].x); acc[3].y = fmaf(w3, v4.y, acc[3].y);
            acc[3].z = fmaf(w3, v4.z, acc[3].z); acc[3].w = fmaf(w3, v4.w, acc[3].w);
        }
    }

    __syncthreads();
    #pragma unroll
    for (int c = 0; c < 4; c++)
        *(float4*)&k_sm[(qA + c) * 68 + d0] = acc[c];
    __syncthreads();

    const int d    = tid & 63;
    const int part = tid >> 6;
    float s = 0.f;
    #pragma unroll
    for (int r = part * 16; r < part * 16 + 16; r++)
        s += k_sm[r * 68 + d];
    v_sm[part * 64 + d] = s;
    __syncthreads();
    if (tid < 64) {
        float tot = v_sm[tid] + v_sm[64 + tid] + v_sm[128 + tid] + v_sm[192 + tid];
        g_part[((b * NTILE) + tile) * DM + h * HD + tid] = tot;
    }
}

// ---------------------------------------------------------------------------
__global__ __launch_bounds__(256) void fc_kernel(
    const float* __restrict__ Wfc, const float* __restrict__ bfc,
    float* __restrict__ out)
{
    __shared__ float pooled[DM];
    const int b   = blockIdx.y;
    const int tid = threadIdx.x;

    for (int i = tid; i < DM; i += 256) {
        float s = 0.f;
        #pragma unroll
        for (int t = 0; t < NTILE; t++)
            s += g_part[(b * NTILE + t) * DM + i];
        pooled[i] = s * (1.0f / (float)S_LEN);
    }
    __syncthreads();

    const int o = blockIdx.x * 256 + tid;
    float acc = bfc[o];
    for (int i = 0; i < DM; i++)
        acc = fmaf(pooled[i], Wfc[i * DM + o], acc);
    out[b * DM + o] = fmaxf(acc, 0.f);
}

// ---------------------------------------------------------------------------
extern "C" void kernel_launch(void* const* d_in, const int* in_sizes, int n_in,
                              void* d_out, int out_size)
{
    const float* x   = (const float*)d_in[0];
    const float* Wq  = (const float*)d_in[1];
    const float* bq  = (const float*)d_in[2];
    const float* Wk  = (const float*)d_in[3];
    const float* bk  = (const float*)d_in[4];
    const float* Wv  = (const float*)d_in[5];
    const float* bv  = (const float*)d_in[6];
    const float* Wfc = (const float*)d_in[7];
    const float* bfc = (const float*)d_in[8];
    float* out = (float*)d_out;

    // fp16 2-term split conversion
    conv_x<<<(MROWS * DM) / 256, 256>>>(x);
    conv_w<<<dim3(DM / 32, DM / 32, 3), dim3(32, 8)>>>(Wq, Wk, Wv);

    // fp16 HMMA GEMMs
    tc_gemm<<<dim3(DM / 128, MROWS / 128, 3), 256>>>(bq, bk, bv);

    // Windowed attention + per-tile pooling (87040 B dynamic smem)
    const int attn_smem = (64 + 128 + 128) * 68 * (int)sizeof(float);
    cudaFuncSetAttribute(attn_kernel,
                         cudaFuncAttributeMaxDynamicSharedMemorySize, attn_smem);
    attn_kernel<<<dim3(NTILE, NH, BATCH), 256, attn_smem>>>();

    fc_kernel<<<dim3(3, BATCH), 256>>>(Wfc, bfc, out);
}

// round 11
// speedup vs baseline: 2.4952x; 1.0599x over previous
#include <cuda_runtime.h>
#include <cuda_fp16.h>
#include <cstdint>

// Problem constants
#define S_LEN 1024
#define BATCH 2
#define DM    768
#define NH    12
#define HD    64
#define NTILE 16
#define MROWS (BATCH * S_LEN)   // 2048
#define KP    1536              // fp16 2-term split: A'=[hi|lo], W'=[hi|hi]
#define NCHUNK (KP / 32)        // 48

// Scratch (device globals — no allocation allowed)
__device__ float g_q[MROWS * DM];
__device__ float g_k[MROWS * DM];
__device__ float g_v[MROWS * DM];
__device__ float g_part[BATCH * NTILE * DM];
__device__ __half g_ahl[MROWS * KP];        // A' = [hi(x) | lo(x)]
__device__ __half g_wt[3 * DM * KP];        // W'^T = [hi | hi], [n][k'] K-major

// ---------------- PTX helpers (portable: ldmatrix + mma.sync) ----------------
__device__ __forceinline__ uint32_t smem_u32(const void* p) {
    uint32_t a;
    asm("{ .reg .u64 t; cvta.to.shared.u64 t, %1; cvt.u32.u64 %0, t; }"
        : "=r"(a) : "l"(p));
    return a;
}
__device__ __forceinline__ void ldsm_x4(uint32_t& r0, uint32_t& r1,
                                        uint32_t& r2, uint32_t& r3, uint32_t addr) {
    asm volatile("ldmatrix.sync.aligned.m8n8.x4.shared.b16 {%0,%1,%2,%3}, [%4];"
                 : "=r"(r0), "=r"(r1), "=r"(r2), "=r"(r3) : "r"(addr));
}
__device__ __forceinline__ void mma16816(float* c, uint32_t a0, uint32_t a1,
                                         uint32_t a2, uint32_t a3,
                                         uint32_t b0, uint32_t b1) {
    asm volatile("mma.sync.aligned.m16n8k16.row.col.f32.f16.f16.f32 "
                 "{%0,%1,%2,%3}, {%4,%5,%6,%7}, {%8,%9}, {%0,%1,%2,%3};"
                 : "+f"(c[0]), "+f"(c[1]), "+f"(c[2]), "+f"(c[3])
                 : "r"(a0), "r"(a1), "r"(a2), "r"(a3), "r"(b0), "r"(b1));
}

// ---------------------------------------------------------------------------
// Convert x -> A' = [hi | lo] along K'
// ---------------------------------------------------------------------------
__global__ __launch_bounds__(256) void conv_x(const float* __restrict__ x)
{
    int i = blockIdx.x * 256 + threadIdx.x;
    float a = x[i];
    __half hi = __float2half_rn(a);
    __half lo = __float2half_rn(a - __half2float(hi));
    int m = i / DM;
    int k = i - m * DM;
    __half* row = g_ahl + (size_t)m * KP;
    row[k]      = hi;
    row[DM + k] = lo;
}

// ---------------------------------------------------------------------------
// Convert + transpose W[k][n] -> Wt[n] = [hi | hi] along K' (per z)
// ---------------------------------------------------------------------------
__global__ __launch_bounds__(256) void conv_w(
    const float* __restrict__ Wq, const float* __restrict__ Wk,
    const float* __restrict__ Wv)
{
    __shared__ float tile[32][33];
    const int z  = blockIdx.z;
    const float* W = (z == 0) ? Wq : (z == 1) ? Wk : Wv;
    __half* out = g_wt + (size_t)z * DM * KP;
    const int k0 = blockIdx.x * 32;
    const int n0 = blockIdx.y * 32;
    const int tx = threadIdx.x;
    const int ty = threadIdx.y;

    #pragma unroll
    for (int r = ty; r < 32; r += 8)
        tile[r][tx] = W[(k0 + r) * DM + n0 + tx];
    __syncthreads();
    #pragma unroll
    for (int r = ty; r < 32; r += 8) {
        float v = tile[tx][r];
        __half hi = __float2half_rn(v);
        __half* row = out + (size_t)(n0 + r) * KP;
        row[k0 + tx]      = hi;
        row[DM + k0 + tx] = hi;
    }
}

// ---------------------------------------------------------------------------
// fp16 HMMA GEMM: C[2048x768] = A'[2048x1536] @ Wt^T + bias, per z.
// ---------------------------------------------------------------------------
#define LDA 40

__global__ __launch_bounds__(256, 2) void tc_gemm(
    const float* __restrict__ bq, const float* __restrict__ bk,
    const float* __restrict__ bv)
{
    __shared__ __half As[2][128 * LDA];
    __shared__ __half Bs[2][128 * LDA];

    const int tid  = threadIdx.x;
    const int warp = tid >> 5;
    const int lane = tid & 31;
    const int wm = warp >> 2;
    const int wn = warp & 3;

    const int z  = blockIdx.z;
    const int n0 = blockIdx.x * 128;
    const int m0 = blockIdx.y * 128;
    const float* bias = (z == 0) ? bq : (z == 1) ? bk : bv;
    float* C = (z == 0) ? g_q : (z == 1) ? g_k : g_v;
    const __half* Wt = g_wt + (size_t)z * DM * KP;

    const int f0   = tid;
    const int row0 = f0 >> 2,  q0 = f0 & 3;
    const int row1 = (f0 + 256) >> 2, q1 = (f0 + 256) & 3;

    const __half* Ag = g_ahl + (size_t)m0 * KP;
    const __half* Bg = Wt    + (size_t)n0 * KP;

    const int a_r = lane & 15, a_c = (lane >> 4) * 8;
    const int b_n = (lane & 7) + ((lane >> 4) << 3);
    const int b_k = ((lane >> 3) & 1) * 8;

    const uint32_t asm_base = smem_u32(&As[0][0]);
    const uint32_t bsm_base = smem_u32(&Bs[0][0]);
    const uint32_t buf_bytes = 128 * LDA * 2;

    float acc[4][4][4];
    #pragma unroll
    for (int i = 0; i < 4; i++)
        #pragma unroll
        for (int j = 0; j < 4; j++)
            #pragma unroll
            for (int r = 0; r < 4; r++) acc[i][j][r] = 0.0f;

    {
        *(float4*)&As[0][row0 * LDA + q0 * 8] = *(const float4*)(Ag + (size_t)row0 * KP + q0 * 8);
        *(float4*)&As[0][row1 * LDA + q1 * 8] = *(const float4*)(Ag + (size_t)row1 * KP + q1 * 8);
        *(float4*)&Bs[0][row0 * LDA + q0 * 8] = *(const float4*)(Bg + (size_t)row0 * KP + q0 * 8);
        *(float4*)&Bs[0][row1 * LDA + q1 * 8] = *(const float4*)(Bg + (size_t)row1 * KP + q1 * 8);
    }
    __syncthreads();

    int buf = 0;
    for (int c = 0; c < NCHUNK; c++) {
        const bool has_next = (c + 1) < NCHUNK;
        float4 pA0, pA1, pB0, pB1;
        if (has_next) {
            const size_t ko = (size_t)(c + 1) * 32;
            pA0 = *(const float4*)(Ag + (size_t)row0 * KP + ko + q0 * 8);
            pA1 = *(const float4*)(Ag + (size_t)row1 * KP + ko + q1 * 8);
            pB0 = *(const float4*)(Bg + (size_t)row0 * KP + ko + q0 * 8);
            pB1 = *(const float4*)(Bg + (size_t)row1 * KP + ko + q1 * 8);
        }

        const uint32_t ab = asm_base + buf * buf_bytes;
        const uint32_t bb = bsm_base + buf * buf_bytes;
        #pragma unroll
        for (int ks = 0; ks < 2; ks++) {
            const int k0 = ks * 16;
            uint32_t a[4][4];
            #pragma unroll
            for (int mt = 0; mt < 4; mt++) {
                uint32_t addr = ab + ((wm * 64 + mt * 16 + a_r) * LDA + k0 + a_c) * 2;
                ldsm_x4(a[mt][0], a[mt][1], a[mt][2], a[mt][3], addr);
            }
            uint32_t b[2][4];
            #pragma unroll
            for (int np = 0; np < 2; np++) {
                uint32_t addr = bb + ((wn * 32 + np * 16 + b_n) * LDA + k0 + b_k) * 2;
                ldsm_x4(b[np][0], b[np][1], b[np][2], b[np][3], addr);
            }
            #pragma unroll
            for (int mt = 0; mt < 4; mt++)
                #pragma unroll
                for (int nt = 0; nt < 4; nt++)
                    mma16816(acc[mt][nt],
                             a[mt][0], a[mt][1], a[mt][2], a[mt][3],
                             b[nt >> 1][(nt & 1) * 2], b[nt >> 1][(nt & 1) * 2 + 1]);
        }

        if (has_next) {
            const int nb = buf ^ 1;
            *(float4*)&As[nb][row0 * LDA + q0 * 8] = pA0;
            *(float4*)&As[nb][row1 * LDA + q1 * 8] = pA1;
            *(float4*)&Bs[nb][row0 * LDA + q0 * 8] = pB0;
            *(float4*)&Bs[nb][row1 * LDA + q1 * 8] = pB1;
            __syncthreads();
            buf = nb;
        }
    }

    const int g  = lane >> 2;
    const int tg = lane & 3;
    #pragma unroll
    for (int mt = 0; mt < 4; mt++) {
        const int row = m0 + wm * 64 + mt * 16 + g;
        float* Crow0 = C + (size_t)row * DM;
        float* Crow1 = C + (size_t)(row + 8) * DM;
        #pragma unroll
        for (int nt = 0; nt < 4; nt++) {
            const int col = n0 + wn * 32 + nt * 8 + tg * 2;
            const float bx = __ldg(&bias[col]);
            const float by = __ldg(&bias[col + 1]);
            float2 v0 = make_float2(acc[mt][nt][0] + bx, acc[mt][nt][1] + by);
            float2 v1 = make_float2(acc[mt][nt][2] + bx, acc[mt][nt][3] + by);
            *(float2*)&Crow0[col] = v0;
            *(float2*)&Crow1[col] = v1;
        }
    }
}

// ---------------------------------------------------------------------------
// Windowed attention, v5: like v4 (16-lane group owns 4 queries, k-row-indexed
// scores, branch-free AV) but K/V held in smem as fp16 -> smem 51KB and
// __launch_bounds__(256,3) -> 3 CTAs/SM. q, weights, accum stay fp32.
// smem layout (bytes): q_sm f32 [0,17408) | k_sm f16 [17408,34816) |
//                      v_sm f16 [34816,52224)
// reuse: out rows f32 overwrite k region; pool partials overwrite v region.
// ---------------------------------------------------------------------------
__global__ __launch_bounds__(256, 3) void attn_kernel()
{
    const int tile = blockIdx.x;
    const int h    = blockIdx.y;
    const int b    = blockIdx.z;
    const int s0   = tile * 64;
    const int colbase = h * HD;

    extern __shared__ __align__(16) char smraw[];
    float*  q_sm = (float*)smraw;                       // 64 x 68 f32
    __half* k_sm = (__half*)(smraw + 17408);            // 128 x 68 f16
    __half* v_sm = (__half*)(smraw + 34816);            // 128 x 68 f16
    float*  o_sm = (float*)(smraw + 17408);             // 64 x 68 f32 (reuse k)
    float*  p_sm = (float*)(smraw + 34816);             // 4 x 64 f32 (reuse v)

    const int tid = threadIdx.x;

    // Load Q tile (fp32)
    for (int i = tid; i < 64 * 16; i += 256) {
        int row = i >> 4;
        int c4  = (i & 15) << 2;
        float4 v = *(const float4*)&g_q[((b * S_LEN) + s0 + row) * DM + colbase + c4];
        *(float4*)&q_sm[row * 68 + c4] = v;
    }
    // Load K/V window as fp16 (rows s0-32 .. s0+95), zero-fill out of range
    for (int i = tid; i < 128 * 16; i += 256) {
        int row  = i >> 4;
        int c4   = (i & 15) << 2;
        int srow = s0 - 32 + row;
        float4 kv = make_float4(0.f, 0.f, 0.f, 0.f);
        float4 vv = make_float4(0.f, 0.f, 0.f, 0.f);
        if (srow >= 0 && srow < S_LEN) {
            kv = *(const float4*)&g_k[((b * S_LEN) + srow) * DM + colbase + c4];
            vv = *(const float4*)&g_v[((b * S_LEN) + srow) * DM + colbase + c4];
        }
        __half2 k01 = __floats2half2_rn(kv.x, kv.y);
        __half2 k23 = __floats2half2_rn(kv.z, kv.w);
        __half2 v01 = __floats2half2_rn(vv.x, vv.y);
        __half2 v23 = __floats2half2_rn(vv.z, vv.w);
        uint2 ku, vu;
        ku.x = *(uint32_t*)&k01; ku.y = *(uint32_t*)&k23;
        vu.x = *(uint32_t*)&v01; vu.y = *(uint32_t*)&v23;
        *(uint2*)&k_sm[row * 68 + c4] = ku;
        *(uint2*)&v_sm[row * 68 + c4] = vu;
    }
    __syncthreads();

    const int grp = tid >> 4;       // 0..15 query-quad group
    const int sub = tid & 15;       // lane within group
    const int qA  = grp * 4;

    int ro[5];
    #pragma unroll
    for (int j = 0; j < 5; j++) {
        int rsm = qA + sub + 16 * j;
        if (rsm > 127) rsm = 127;
        ro[j] = rsm * 68;
    }

    float sc[5][4];
    #pragma unroll
    for (int j = 0; j < 5; j++)
        #pragma unroll
        for (int c = 0; c < 4; c++) sc[j][c] = 0.f;

    #pragma unroll
    for (int dc = 0; dc < 16; dc++) {
        float4 qv[4];
        #pragma unroll
        for (int c = 0; c < 4; c++)
            qv[c] = *(const float4*)&q_sm[(qA + c) * 68 + dc * 4];
        #pragma unroll
        for (int j = 0; j < 5; j++) {
            uint2 kraw = *(const uint2*)&k_sm[ro[j] + dc * 4];
            float2 k01 = __half22float2(*(__half2*)&kraw.x);
            float2 k23 = __half22float2(*(__half2*)&kraw.y);
            #pragma unroll
            for (int c = 0; c < 4; c++) {
                sc[j][c] = fmaf(qv[c].x, k01.x, sc[j][c]);
                sc[j][c] = fmaf(qv[c].y, k01.y, sc[j][c]);
                sc[j][c] = fmaf(qv[c].z, k23.x, sc[j][c]);
                sc[j][c] = fmaf(qv[c].w, k23.y, sc[j][c]);
            }
        }
    }

    #pragma unroll
    for (int j = 0; j < 5; j++) {
        int rsm = qA + sub + 16 * j;
        int gk  = s0 + rsm - 32;
        bool rowok = (rsm <= 127) && (gk >= 0) && (gk < S_LEN);
        #pragma unroll
        for (int c = 0; c < 4; c++) {
            int w = sub + 16 * j - c;
            bool ok = rowok && (w >= 0) && (w <= 64);
            sc[j][c] = ok ? sc[j][c] * 0.125f : -1e9f;
        }
    }

    float mx[4], lsum[4];
    #pragma unroll
    for (int c = 0; c < 4; c++) {
        float m = -1e30f;
        #pragma unroll
        for (int j = 0; j < 5; j++) m = fmaxf(m, sc[j][c]);
        #pragma unroll
        for (int o = 1; o <= 8; o <<= 1)
            m = fmaxf(m, __shfl_xor_sync(0xffffffffu, m, o, 16));
        mx[c] = m;
    }
    #pragma unroll
    for (int c = 0; c < 4; c++) {
        float l = 0.f;
        #pragma unroll
        for (int j = 0; j < 5; j++) { sc[j][c] = __expf(sc[j][c] - mx[c]); l += sc[j][c]; }
        #pragma unroll
        for (int o = 1; o <= 8; o <<= 1)
            l += __shfl_xor_sync(0xffffffffu, l, o, 16);
        lsum[c] = 1.0f / l;
    }

    // weights -> q_sm rows (slot = sub+16j, invalid entries 0-weighted)
    #pragma unroll
    for (int j = 0; j < 5; j++) {
        int slot = sub + 16 * j;
        if (slot < 68) {
            #pragma unroll
            for (int c = 0; c < 4; c++)
                q_sm[(qA + c) * 68 + slot] = sc[j][c] * lsum[c];
        }
    }
    __syncwarp();

    // ---- AV: lane owns dims sub*4..sub*4+3 for all 4 queries; v is fp16 ----
    const int d0 = sub * 4;
    float4 acc[4];
    #pragma unroll
    for (int c = 0; c < 4; c++) acc[c] = make_float4(0.f, 0.f, 0.f, 0.f);

    #pragma unroll
    for (int tb = 0; tb < 17; tb++) {
        float4 wv[4];
        #pragma unroll
        for (int c = 0; c < 4; c++)
            wv[c] = *(const float4*)&q_sm[(qA + c) * 68 + tb * 4];
        #pragma unroll
        for (int s = 0; s < 4; s++) {
            int t = tb * 4 + s;
            uint2 vraw = *(const uint2*)&v_sm[(qA + t) * 68 + d0];
            float2 v01 = __half22float2(*(__half2*)&vraw.x);
            float2 v23 = __half22float2(*(__half2*)&vraw.y);
            float w0 = (s == 0) ? wv[0].x : (s == 1) ? wv[0].y : (s == 2) ? wv[0].z : wv[0].w;
            float w1 = (s == 0) ? wv[1].x : (s == 1) ? wv[1].y : (s == 2) ? wv[1].z : wv[1].w;
            float w2 = (s == 0) ? wv[2].x : (s == 1) ? wv[2].y : (s == 2) ? wv[2].z : wv[2].w;
            float w3 = (s == 0) ? wv[3].x : (s == 1) ? wv[3].y : (s == 2) ? wv[3].z : wv[3].w;
            acc[0].x = fmaf(w0, v01.x, acc[0].x); acc[0].y = fmaf(w0, v01.y, acc[0].y);
            acc[0].z = fmaf(w0, v23.x, acc[0].z); acc[0].w = fmaf(w0, v23.y, acc[0].w);
            acc[1].x = fmaf(w1, v01.x, acc[1].x); acc[1].y = fmaf(w1, v01.y, acc[1].y);
            acc[1].z = fmaf(w1, v23.x, acc[1].z); acc[1].w = fmaf(w1, v23.y, acc[1].w);
            acc[2].x = fmaf(w2, v01.x, acc[2].x); acc[2].y = fmaf(w2, v01.y, acc[2].y);
            acc[2].z = fmaf(w2, v23.x, acc[2].z); acc[2].w = fmaf(w2, v23.y, acc[2].w);
            acc[3].x = fmaf(w3, v01.x, acc[3].x); acc[3].y = fmaf(w3, v01.y, acc[3].y);
            acc[3].z = fmaf(w3, v23.x, acc[3].z); acc[3].w = fmaf(w3, v23.y, acc[3].w);
        }
    }

    __syncthreads();     // all k/v/weight reads done before reusing regions
    #pragma unroll
    for (int c = 0; c < 4; c++)
        *(float4*)&o_sm[(qA + c) * 68 + d0] = acc[c];
    __syncthreads();

    // ---- pooled partial: 4 parts x 16 rows ----
    const int d    = tid & 63;
    const int part = tid >> 6;
    float s = 0.f;
    #pragma unroll
    for (int r = part * 16; r < part * 16 + 16; r++)
        s += o_sm[r * 68 + d];
    p_sm[part * 64 + d] = s;
    __syncthreads();
    if (tid < 64) {
        float tot = p_sm[tid] + p_sm[64 + tid] + p_sm[128 + tid] + p_sm[192 + tid];
        g_part[((b * NTILE) + tile) * DM + h * HD + tid] = tot;
    }
}

// ---------------------------------------------------------------------------
__global__ __launch_bounds__(256) void fc_kernel(
    const float* __restrict__ Wfc, const float* __restrict__ bfc,
    float* __restrict__ out)
{
    __shared__ float pooled[DM];
    const int b   = blockIdx.y;
    const int tid = threadIdx.x;

    for (int i = tid; i < DM; i += 256) {
        float s = 0.f;
        #pragma unroll
        for (int t = 0; t < NTILE; t++)
            s += g_part[(b * NTILE + t) * DM + i];
        pooled[i] = s * (1.0f / (float)S_LEN);
    }
    __syncthreads();

    const int o = blockIdx.x * 256 + tid;
    float acc = bfc[o];
    for (int i = 0; i < DM; i++)
        acc = fmaf(pooled[i], Wfc[i * DM + o], acc);
    out[b * DM + o] = fmaxf(acc, 0.f);
}

// ---------------------------------------------------------------------------
extern "C" void kernel_launch(void* const* d_in, const int* in_sizes, int n_in,
                              void* d_out, int out_size)
{
    const float* x   = (const float*)d_in[0];
    const float* Wq  = (const float*)d_in[1];
    const float* bq  = (const float*)d_in[2];
    const float* Wk  = (const float*)d_in[3];
    const float* bk  = (const float*)d_in[4];
    const float* Wv  = (const float*)d_in[5];
    const float* bv  = (const float*)d_in[6];
    const float* Wfc = (const float*)d_in[7];
    const float* bfc = (const float*)d_in[8];
    float* out = (float*)d_out;

    // fp16 2-term split conversion
    conv_x<<<(MROWS * DM) / 256, 256>>>(x);
    conv_w<<<dim3(DM / 32, DM / 32, 3), dim3(32, 8)>>>(Wq, Wk, Wv);

    // fp16 HMMA GEMMs
    tc_gemm<<<dim3(DM / 128, MROWS / 128, 3), 256>>>(bq, bk, bv);

    // Windowed attention + per-tile pooling (52224 B dynamic smem, 3 CTAs/SM)
    const int attn_smem = 52224;
    cudaFuncSetAttribute(attn_kernel,
                         cudaFuncAttributeMaxDynamicSharedMemorySize, attn_smem);
    attn_kernel<<<dim3(NTILE, NH, BATCH), 256, attn_smem>>>();

    fc_kernel<<<dim3(3, BATCH), 256>>>(Wfc, bfc, out);
}

// round 12
// speedup vs baseline: 3.2668x; 1.3092x over previous
#include <cuda_runtime.h>
#include <cuda_fp16.h>
#include <cstdint>

// Problem constants
#define S_LEN 1024
#define BATCH 2
#define DM    768
#define NH    12
#define HD    64
#define NTILE 16
#define MROWS (BATCH * S_LEN)   // 2048
#define KP    768               // plain fp16 GEMM (no split)
#define NCHUNK (KP / 32)        // 24

// Scratch (device globals — no allocation allowed)
__device__ float g_q[MROWS * DM];
__device__ float g_k[MROWS * DM];
__device__ float g_v[MROWS * DM];
__device__ float g_part[BATCH * NTILE * DM];
__device__ __half g_ahl[MROWS * KP];        // fp16(x)
__device__ __half g_wt[3 * DM * KP];        // fp16(W)^T per gemm: [n][k] K-major

// ---------------- PTX helpers (portable: ldmatrix + mma.sync) ----------------
__device__ __forceinline__ uint32_t smem_u32(const void* p) {
    uint32_t a;
    asm("{ .reg .u64 t; cvta.to.shared.u64 t, %1; cvt.u32.u64 %0, t; }"
        : "=r"(a) : "l"(p));
    return a;
}
__device__ __forceinline__ void ldsm_x4(uint32_t& r0, uint32_t& r1,
                                        uint32_t& r2, uint32_t& r3, uint32_t addr) {
    asm volatile("ldmatrix.sync.aligned.m8n8.x4.shared.b16 {%0,%1,%2,%3}, [%4];"
                 : "=r"(r0), "=r"(r1), "=r"(r2), "=r"(r3) : "r"(addr));
}
__device__ __forceinline__ void mma16816(float* c, uint32_t a0, uint32_t a1,
                                         uint32_t a2, uint32_t a3,
                                         uint32_t b0, uint32_t b1) {
    asm volatile("mma.sync.aligned.m16n8k16.row.col.f32.f16.f16.f32 "
                 "{%0,%1,%2,%3}, {%4,%5,%6,%7}, {%8,%9}, {%0,%1,%2,%3};"
                 : "+f"(c[0]), "+f"(c[1]), "+f"(c[2]), "+f"(c[3])
                 : "r"(a0), "r"(a1), "r"(a2), "r"(a3), "r"(b0), "r"(b1));
}

// ---------------------------------------------------------------------------
// Convert x -> fp16
// ---------------------------------------------------------------------------
__global__ __launch_bounds__(256) void conv_x(const float* __restrict__ x)
{
    int i = blockIdx.x * 256 + threadIdx.x;
    g_ahl[i] = __float2half_rn(x[i]);
}

// ---------------------------------------------------------------------------
// Convert + transpose W[k][n] -> Wt[n][k] fp16 (per z)
// ---------------------------------------------------------------------------
__global__ __launch_bounds__(256) void conv_w(
    const float* __restrict__ Wq, const float* __restrict__ Wk,
    const float* __restrict__ Wv)
{
    __shared__ float tile[32][33];
    const int z  = blockIdx.z;
    const float* W = (z == 0) ? Wq : (z == 1) ? Wk : Wv;
    __half* out = g_wt + (size_t)z * DM * KP;
    const int k0 = blockIdx.x * 32;
    const int n0 = blockIdx.y * 32;
    const int tx = threadIdx.x;
    const int ty = threadIdx.y;

    #pragma unroll
    for (int r = ty; r < 32; r += 8)
        tile[r][tx] = W[(k0 + r) * DM + n0 + tx];
    __syncthreads();
    #pragma unroll
    for (int r = ty; r < 32; r += 8)
        out[(size_t)(n0 + r) * KP + (k0 + tx)] = __float2half_rn(tile[tx][r]);
}

// ---------------------------------------------------------------------------
// fp16 HMMA GEMM: C[2048x768] = A[2048x768] @ Wt^T + bias, per z.
// CTA 128x128, BK=32, 8 warps (2x4), warp tile 64x32, mma.sync m16n8k16.
// ---------------------------------------------------------------------------
#define LDA 40

__global__ __launch_bounds__(256, 2) void tc_gemm(
    const float* __restrict__ bq, const float* __restrict__ bk,
    const float* __restrict__ bv)
{
    __shared__ __half As[2][128 * LDA];
    __shared__ __half Bs[2][128 * LDA];

    const int tid  = threadIdx.x;
    const int warp = tid >> 5;
    const int lane = tid & 31;
    const int wm = warp >> 2;
    const int wn = warp & 3;

    const int z  = blockIdx.z;
    const int n0 = blockIdx.x * 128;
    const int m0 = blockIdx.y * 128;
    const float* bias = (z == 0) ? bq : (z == 1) ? bk : bv;
    float* C = (z == 0) ? g_q : (z == 1) ? g_k : g_v;
    const __half* Wt = g_wt + (size_t)z * DM * KP;

    const int f0   = tid;
    const int row0 = f0 >> 2,  q0 = f0 & 3;
    const int row1 = (f0 + 256) >> 2, q1 = (f0 + 256) & 3;

    const __half* Ag = g_ahl + (size_t)m0 * KP;
    const __half* Bg = Wt    + (size_t)n0 * KP;

    const int a_r = lane & 15, a_c = (lane >> 4) * 8;
    const int b_n = (lane & 7) + ((lane >> 4) << 3);
    const int b_k = ((lane >> 3) & 1) * 8;

    const uint32_t asm_base = smem_u32(&As[0][0]);
    const uint32_t bsm_base = smem_u32(&Bs[0][0]);
    const uint32_t buf_bytes = 128 * LDA * 2;

    float acc[4][4][4];
    #pragma unroll
    for (int i = 0; i < 4; i++)
        #pragma unroll
        for (int j = 0; j < 4; j++)
            #pragma unroll
            for (int r = 0; r < 4; r++) acc[i][j][r] = 0.0f;

    {
        *(float4*)&As[0][row0 * LDA + q0 * 8] = *(const float4*)(Ag + (size_t)row0 * KP + q0 * 8);
        *(float4*)&As[0][row1 * LDA + q1 * 8] = *(const float4*)(Ag + (size_t)row1 * KP + q1 * 8);
        *(float4*)&Bs[0][row0 * LDA + q0 * 8] = *(const float4*)(Bg + (size_t)row0 * KP + q0 * 8);
        *(float4*)&Bs[0][row1 * LDA + q1 * 8] = *(const float4*)(Bg + (size_t)row1 * KP + q1 * 8);
    }
    __syncthreads();

    int buf = 0;
    for (int c = 0; c < NCHUNK; c++) {
        const bool has_next = (c + 1) < NCHUNK;
        float4 pA0, pA1, pB0, pB1;
        if (has_next) {
            const size_t ko = (size_t)(c + 1) * 32;
            pA0 = *(const float4*)(Ag + (size_t)row0 * KP + ko + q0 * 8);
            pA1 = *(const float4*)(Ag + (size_t)row1 * KP + ko + q1 * 8);
            pB0 = *(const float4*)(Bg + (size_t)row0 * KP + ko + q0 * 8);
            pB1 = *(const float4*)(Bg + (size_t)row1 * KP + ko + q1 * 8);
        }

        const uint32_t ab = asm_base + buf * buf_bytes;
        const uint32_t bb = bsm_base + buf * buf_bytes;
        #pragma unroll
        for (int ks = 0; ks < 2; ks++) {
            const int k0 = ks * 16;
            uint32_t a[4][4];
            #pragma unroll
            for (int mt = 0; mt < 4; mt++) {
                uint32_t addr = ab + ((wm * 64 + mt * 16 + a_r) * LDA + k0 + a_c) * 2;
                ldsm_x4(a[mt][0], a[mt][1], a[mt][2], a[mt][3], addr);
            }
            uint32_t b[2][4];
            #pragma unroll
            for (int np = 0; np < 2; np++) {
                uint32_t addr = bb + ((wn * 32 + np * 16 + b_n) * LDA + k0 + b_k) * 2;
                ldsm_x4(b[np][0], b[np][1], b[np][2], b[np][3], addr);
            }
            #pragma unroll
            for (int mt = 0; mt < 4; mt++)
                #pragma unroll
                for (int nt = 0; nt < 4; nt++)
                    mma16816(acc[mt][nt],
                             a[mt][0], a[mt][1], a[mt][2], a[mt][3],
                             b[nt >> 1][(nt & 1) * 2], b[nt >> 1][(nt & 1) * 2 + 1]);
        }

        if (has_next) {
            const int nb = buf ^ 1;
            *(float4*)&As[nb][row0 * LDA + q0 * 8] = pA0;
            *(float4*)&As[nb][row1 * LDA + q1 * 8] = pA1;
            *(float4*)&Bs[nb][row0 * LDA + q0 * 8] = pB0;
            *(float4*)&Bs[nb][row1 * LDA + q1 * 8] = pB1;
            __syncthreads();
            buf = nb;
        }
    }

    const int g  = lane >> 2;
    const int tg = lane & 3;
    #pragma unroll
    for (int mt = 0; mt < 4; mt++) {
        const int row = m0 + wm * 64 + mt * 16 + g;
        float* Crow0 = C + (size_t)row * DM;
        float* Crow1 = C + (size_t)(row + 8) * DM;
        #pragma unroll
        for (int nt = 0; nt < 4; nt++) {
            const int col = n0 + wn * 32 + nt * 8 + tg * 2;
            const float bx = __ldg(&bias[col]);
            const float by = __ldg(&bias[col + 1]);
            float2 v0 = make_float2(acc[mt][nt][0] + bx, acc[mt][nt][1] + by);
            float2 v1 = make_float2(acc[mt][nt][2] + bx, acc[mt][nt][3] + by);
            *(float2*)&Crow0[col] = v0;
            *(float2*)&Crow1[col] = v1;
        }
    }
}

// ---------------------------------------------------------------------------
// Windowed attention, v5 (unchanged from R11): 16-lane group owns 4 queries,
// fp16 K/V in smem, 3 CTAs/SM.
// ---------------------------------------------------------------------------
__global__ __launch_bounds__(256, 3) void attn_kernel()
{
    const int tile = blockIdx.x;
    const int h    = blockIdx.y;
    const int b    = blockIdx.z;
    const int s0   = tile * 64;
    const int colbase = h * HD;

    extern __shared__ __align__(16) char smraw[];
    float*  q_sm = (float*)smraw;                       // 64 x 68 f32
    __half* k_sm = (__half*)(smraw + 17408);            // 128 x 68 f16
    __half* v_sm = (__half*)(smraw + 34816);            // 128 x 68 f16
    float*  o_sm = (float*)(smraw + 17408);             // reuse k region
    float*  p_sm = (float*)(smraw + 34816);             // reuse v region

    const int tid = threadIdx.x;

    for (int i = tid; i < 64 * 16; i += 256) {
        int row = i >> 4;
        int c4  = (i & 15) << 2;
        float4 v = *(const float4*)&g_q[((b * S_LEN) + s0 + row) * DM + colbase + c4];
        *(float4*)&q_sm[row * 68 + c4] = v;
    }
    for (int i = tid; i < 128 * 16; i += 256) {
        int row  = i >> 4;
        int c4   = (i & 15) << 2;
        int srow = s0 - 32 + row;
        float4 kv = make_float4(0.f, 0.f, 0.f, 0.f);
        float4 vv = make_float4(0.f, 0.f, 0.f, 0.f);
        if (srow >= 0 && srow < S_LEN) {
            kv = *(const float4*)&g_k[((b * S_LEN) + srow) * DM + colbase + c4];
            vv = *(const float4*)&g_v[((b * S_LEN) + srow) * DM + colbase + c4];
        }
        __half2 k01 = __floats2half2_rn(kv.x, kv.y);
        __half2 k23 = __floats2half2_rn(kv.z, kv.w);
        __half2 v01 = __floats2half2_rn(vv.x, vv.y);
        __half2 v23 = __floats2half2_rn(vv.z, vv.w);
        uint2 ku, vu;
        ku.x = *(uint32_t*)&k01; ku.y = *(uint32_t*)&k23;
        vu.x = *(uint32_t*)&v01; vu.y = *(uint32_t*)&v23;
        *(uint2*)&k_sm[row * 68 + c4] = ku;
        *(uint2*)&v_sm[row * 68 + c4] = vu;
    }
    __syncthreads();

    const int grp = tid >> 4;
    const int sub = tid & 15;
    const int qA  = grp * 4;

    int ro[5];
    #pragma unroll
    for (int j = 0; j < 5; j++) {
        int rsm = qA + sub + 16 * j;
        if (rsm > 127) rsm = 127;
        ro[j] = rsm * 68;
    }

    float sc[5][4];
    #pragma unroll
    for (int j = 0; j < 5; j++)
        #pragma unroll
        for (int c = 0; c < 4; c++) sc[j][c] = 0.f;

    #pragma unroll
    for (int dc = 0; dc < 16; dc++) {
        float4 qv[4];
        #pragma unroll
        for (int c = 0; c < 4; c++)
            qv[c] = *(const float4*)&q_sm[(qA + c) * 68 + dc * 4];
        #pragma unroll
        for (int j = 0; j < 5; j++) {
            uint2 kraw = *(const uint2*)&k_sm[ro[j] + dc * 4];
            float2 k01 = __half22float2(*(__half2*)&kraw.x);
            float2 k23 = __half22float2(*(__half2*)&kraw.y);
            #pragma unroll
            for (int c = 0; c < 4; c++) {
                sc[j][c] = fmaf(qv[c].x, k01.x, sc[j][c]);
                sc[j][c] = fmaf(qv[c].y, k01.y, sc[j][c]);
                sc[j][c] = fmaf(qv[c].z, k23.x, sc[j][c]);
                sc[j][c] = fmaf(qv[c].w, k23.y, sc[j][c]);
            }
        }
    }

    #pragma unroll
    for (int j = 0; j < 5; j++) {
        int rsm = qA + sub + 16 * j;
        int gk  = s0 + rsm - 32;
        bool rowok = (rsm <= 127) && (gk >= 0) && (gk < S_LEN);
        #pragma unroll
        for (int c = 0; c < 4; c++) {
            int w = sub + 16 * j - c;
            bool ok = rowok && (w >= 0) && (w <= 64);
            sc[j][c] = ok ? sc[j][c] * 0.125f : -1e9f;
        }
    }

    float mx[4], lsum[4];
    #pragma unroll
    for (int c = 0; c < 4; c++) {
        float m = -1e30f;
        #pragma unroll
        for (int j = 0; j < 5; j++) m = fmaxf(m, sc[j][c]);
        #pragma unroll
        for (int o = 1; o <= 8; o <<= 1)
            m = fmaxf(m, __shfl_xor_sync(0xffffffffu, m, o, 16));
        mx[c] = m;
    }
    #pragma unroll
    for (int c = 0; c < 4; c++) {
        float l = 0.f;
        #pragma unroll
        for (int j = 0; j < 5; j++) { sc[j][c] = __expf(sc[j][c] - mx[c]); l += sc[j][c]; }
        #pragma unroll
        for (int o = 1; o <= 8; o <<= 1)
            l += __shfl_xor_sync(0xffffffffu, l, o, 16);
        lsum[c] = 1.0f / l;
    }

    #pragma unroll
    for (int j = 0; j < 5; j++) {
        int slot = sub + 16 * j;
        if (slot < 68) {
            #pragma unroll
            for (int c = 0; c < 4; c++)
                q_sm[(qA + c) * 68 + slot] = sc[j][c] * lsum[c];
        }
    }
    __syncwarp();

    const int d0 = sub * 4;
    float4 acc[4];
    #pragma unroll
    for (int c = 0; c < 4; c++) acc[c] = make_float4(0.f, 0.f, 0.f, 0.f);

    #pragma unroll
    for (int tb = 0; tb < 17; tb++) {
        float4 wv[4];
        #pragma unroll
        for (int c = 0; c < 4; c++)
            wv[c] = *(const float4*)&q_sm[(qA + c) * 68 + tb * 4];
        #pragma unroll
        for (int s = 0; s < 4; s++) {
            int t = tb * 4 + s;
            uint2 vraw = *(const uint2*)&v_sm[(qA + t) * 68 + d0];
            float2 v01 = __half22float2(*(__half2*)&vraw.x);
            float2 v23 = __half22float2(*(__half2*)&vraw.y);
            float w0 = (s == 0) ? wv[0].x : (s == 1) ? wv[0].y : (s == 2) ? wv[0].z : wv[0].w;
            float w1 = (s == 0) ? wv[1].x : (s == 1) ? wv[1].y : (s == 2) ? wv[1].z : wv[1].w;
            float w2 = (s == 0) ? wv[2].x : (s == 1) ? wv[2].y : (s == 2) ? wv[2].z : wv[2].w;
            float w3 = (s == 0) ? wv[3].x : (s == 1) ? wv[3].y : (s == 2) ? wv[3].z : wv[3].w;
            acc[0].x = fmaf(w0, v01.x, acc[0].x); acc[0].y = fmaf(w0, v01.y, acc[0].y);
            acc[0].z = fmaf(w0, v23.x, acc[0].z); acc[0].w = fmaf(w0, v23.y, acc[0].w);
            acc[1].x = fmaf(w1, v01.x, acc[1].x); acc[1].y = fmaf(w1, v01.y, acc[1].y);
            acc[1].z = fmaf(w1, v23.x, acc[1].z); acc[1].w = fmaf(w1, v23.y, acc[1].w);
            acc[2].x = fmaf(w2, v01.x, acc[2].x); acc[2].y = fmaf(w2, v01.y, acc[2].y);
            acc[2].z = fmaf(w2, v23.x, acc[2].z); acc[2].w = fmaf(w2, v23.y, acc[2].w);
            acc[3].x = fmaf(w3, v01.x, acc[3].x); acc[3].y = fmaf(w3, v01.y, acc[3].y);
            acc[3].z = fmaf(w3, v23.x, acc[3].z); acc[3].w = fmaf(w3, v23.y, acc[3].w);
        }
    }

    __syncthreads();
    #pragma unroll
    for (int c = 0; c < 4; c++)
        *(float4*)&o_sm[(qA + c) * 68 + d0] = acc[c];
    __syncthreads();

    const int d    = tid & 63;
    const int part = tid >> 6;
    float s = 0.f;
    #pragma unroll
    for (int r = part * 16; r < part * 16 + 16; r++)
        s += o_sm[r * 68 + d];
    p_sm[part * 64 + d] = s;
    __syncthreads();
    if (tid < 64) {
        float tot = p_sm[tid] + p_sm[64 + tid] + p_sm[128 + tid] + p_sm[192 + tid];
        g_part[((b * NTILE) + tile) * DM + h * HD + tid] = tot;
    }
}

// ---------------------------------------------------------------------------
__global__ __launch_bounds__(256) void fc_kernel(
    const float* __restrict__ Wfc, const float* __restrict__ bfc,
    float* __restrict__ out)
{
    __shared__ float pooled[DM];
    const int b   = blockIdx.y;
    const int tid = threadIdx.x;

    for (int i = tid; i < DM; i += 256) {
        float s = 0.f;
        #pragma unroll
        for (int t = 0; t < NTILE; t++)
            s += g_part[(b * NTILE + t) * DM + i];
        pooled[i] = s * (1.0f / (float)S_LEN);
    }
    __syncthreads();

    const int o = blockIdx.x * 256 + tid;
    float acc = bfc[o];
    for (int i = 0; i < DM; i++)
        acc = fmaf(pooled[i], Wfc[i * DM + o], acc);
    out[b * DM + o] = fmaxf(acc, 0.f);
}

// ---------------------------------------------------------------------------
extern "C" void kernel_launch(void* const* d_in, const int* in_sizes, int n_in,
                              void* d_out, int out_size)
{
    const float* x   = (const float*)d_in[0];
    const float* Wq  = (const float*)d_in[1];
    const float* bq  = (const float*)d_in[2];
    const float* Wk  = (const float*)d_in[3];
    const float* bk  = (const float*)d_in[4];
    const float* Wv  = (const float*)d_in[5];
    const float* bv  = (const float*)d_in[6];
    const float* Wfc = (const float*)d_in[7];
    const float* bfc = (const float*)d_in[8];
    float* out = (float*)d_out;

    // fp16 conversion (no split)
    conv_x<<<(MROWS * DM) / 256, 256>>>(x);
    conv_w<<<dim3(DM / 32, DM / 32, 3), dim3(32, 8)>>>(Wq, Wk, Wv);

    // fp16 HMMA GEMMs
    tc_gemm<<<dim3(DM / 128, MROWS / 128, 3), 256>>>(bq, bk, bv);

    // Windowed attention + per-tile pooling (52224 B dynamic smem, 3 CTAs/SM)
    const int attn_smem = 52224;
    cudaFuncSetAttribute(attn_kernel,
                         cudaFuncAttributeMaxDynamicSharedMemorySize, attn_smem);
    attn_kernel<<<dim3(NTILE, NH, BATCH), 256, attn_smem>>>();

    fc_kernel<<<dim3(3, BATCH), 256>>>(Wfc, bfc, out);
}

// round 13
// speedup vs baseline: 3.4302x; 1.0500x over previous
#include <cuda_runtime.h>
#include <cuda_fp16.h>
#include <cstdint>

// Problem constants
#define S_LEN 1024
#define BATCH 2
#define DM    768
#define NH    12
#define HD    64
#define NTILE 16
#define MROWS (BATCH * S_LEN)   // 2048
#define KP    768               // plain fp16 GEMM
#define NCHUNK (KP / 32)        // 24

// Scratch (device globals — no allocation allowed)
__device__ float  g_q[MROWS * DM];          // Q stays fp32
__device__ __half g_kh[MROWS * DM];         // K written fp16 by GEMM epilogue
__device__ __half g_vh[MROWS * DM];         // V written fp16 by GEMM epilogue
__device__ float  g_part[BATCH * NTILE * DM];
__device__ __half g_ahl[MROWS * KP];        // fp16(x)
__device__ __half g_wt[3 * DM * KP];        // fp16(W)^T per gemm: [n][k] K-major

// ---------------- PTX helpers ----------------
__device__ __forceinline__ uint32_t smem_u32(const void* p) {
    uint32_t a;
    asm("{ .reg .u64 t; cvta.to.shared.u64 t, %1; cvt.u32.u64 %0, t; }"
        : "=r"(a) : "l"(p));
    return a;
}
__device__ __forceinline__ void ldsm_x4(uint32_t& r0, uint32_t& r1,
                                        uint32_t& r2, uint32_t& r3, uint32_t addr) {
    asm volatile("ldmatrix.sync.aligned.m8n8.x4.shared.b16 {%0,%1,%2,%3}, [%4];"
                 : "=r"(r0), "=r"(r1), "=r"(r2), "=r"(r3) : "r"(addr));
}
__device__ __forceinline__ void mma16816(float* c, uint32_t a0, uint32_t a1,
                                         uint32_t a2, uint32_t a3,
                                         uint32_t b0, uint32_t b1) {
    asm volatile("mma.sync.aligned.m16n8k16.row.col.f32.f16.f16.f32 "
                 "{%0,%1,%2,%3}, {%4,%5,%6,%7}, {%8,%9}, {%0,%1,%2,%3};"
                 : "+f"(c[0]), "+f"(c[1]), "+f"(c[2]), "+f"(c[3])
                 : "r"(a0), "r"(a1), "r"(a2), "r"(a3), "r"(b0), "r"(b1));
}

// ---------------------------------------------------------------------------
__global__ __launch_bounds__(256) void conv_x(const float* __restrict__ x)
{
    int i = blockIdx.x * 256 + threadIdx.x;
    g_ahl[i] = __float2half_rn(x[i]);
}

__global__ __launch_bounds__(256) void conv_w(
    const float* __restrict__ Wq, const float* __restrict__ Wk,
    const float* __restrict__ Wv)
{
    __shared__ float tile[32][33];
    const int z  = blockIdx.z;
    const float* W = (z == 0) ? Wq : (z == 1) ? Wk : Wv;
    __half* out = g_wt + (size_t)z * DM * KP;
    const int k0 = blockIdx.x * 32;
    const int n0 = blockIdx.y * 32;
    const int tx = threadIdx.x;
    const int ty = threadIdx.y;

    #pragma unroll
    for (int r = ty; r < 32; r += 8)
        tile[r][tx] = W[(k0 + r) * DM + n0 + tx];
    __syncthreads();
    #pragma unroll
    for (int r = ty; r < 32; r += 8)
        out[(size_t)(n0 + r) * KP + (k0 + tx)] = __float2half_rn(tile[tx][r]);
}

// ---------------------------------------------------------------------------
// fp16 HMMA GEMM. z=0 -> g_q fp32; z=1/2 -> g_kh/g_vh fp16.
// ---------------------------------------------------------------------------
#define LDA 40

__global__ __launch_bounds__(256, 2) void tc_gemm(
    const float* __restrict__ bq, const float* __restrict__ bk,
    const float* __restrict__ bv)
{
    __shared__ __half As[2][128 * LDA];
    __shared__ __half Bs[2][128 * LDA];

    const int tid  = threadIdx.x;
    const int warp = tid >> 5;
    const int lane = tid & 31;
    const int wm = warp >> 2;
    const int wn = warp & 3;

    const int z  = blockIdx.z;
    const int n0 = blockIdx.x * 128;
    const int m0 = blockIdx.y * 128;
    const float* bias = (z == 0) ? bq : (z == 1) ? bk : bv;
    const __half* Wt = g_wt + (size_t)z * DM * KP;

    const int f0   = tid;
    const int row0 = f0 >> 2,  q0 = f0 & 3;
    const int row1 = (f0 + 256) >> 2, q1 = (f0 + 256) & 3;

    const __half* Ag = g_ahl + (size_t)m0 * KP;
    const __half* Bg = Wt    + (size_t)n0 * KP;

    const int a_r = lane & 15, a_c = (lane >> 4) * 8;
    const int b_n = (lane & 7) + ((lane >> 4) << 3);
    const int b_k = ((lane >> 3) & 1) * 8;

    const uint32_t asm_base = smem_u32(&As[0][0]);
    const uint32_t bsm_base = smem_u32(&Bs[0][0]);
    const uint32_t buf_bytes = 128 * LDA * 2;

    float acc[4][4][4];
    #pragma unroll
    for (int i = 0; i < 4; i++)
        #pragma unroll
        for (int j = 0; j < 4; j++)
            #pragma unroll
            for (int r = 0; r < 4; r++) acc[i][j][r] = 0.0f;

    {
        *(float4*)&As[0][row0 * LDA + q0 * 8] = *(const float4*)(Ag + (size_t)row0 * KP + q0 * 8);
        *(float4*)&As[0][row1 * LDA + q1 * 8] = *(const float4*)(Ag + (size_t)row1 * KP + q1 * 8);
        *(float4*)&Bs[0][row0 * LDA + q0 * 8] = *(const float4*)(Bg + (size_t)row0 * KP + q0 * 8);
        *(float4*)&Bs[0][row1 * LDA + q1 * 8] = *(const float4*)(Bg + (size_t)row1 * KP + q1 * 8);
    }
    __syncthreads();

    int buf = 0;
    for (int c = 0; c < NCHUNK; c++) {
        const bool has_next = (c + 1) < NCHUNK;
        float4 pA0, pA1, pB0, pB1;
        if (has_next) {
            const size_t ko = (size_t)(c + 1) * 32;
            pA0 = *(const float4*)(Ag + (size_t)row0 * KP + ko + q0 * 8);
            pA1 = *(const float4*)(Ag + (size_t)row1 * KP + ko + q1 * 8);
            pB0 = *(const float4*)(Bg + (size_t)row0 * KP + ko + q0 * 8);
            pB1 = *(const float4*)(Bg + (size_t)row1 * KP + ko + q1 * 8);
        }

        const uint32_t ab = asm_base + buf * buf_bytes;
        const uint32_t bb = bsm_base + buf * buf_bytes;
        #pragma unroll
        for (int ks = 0; ks < 2; ks++) {
            const int k0 = ks * 16;
            uint32_t a[4][4];
            #pragma unroll
            for (int mt = 0; mt < 4; mt++) {
                uint32_t addr = ab + ((wm * 64 + mt * 16 + a_r) * LDA + k0 + a_c) * 2;
                ldsm_x4(a[mt][0], a[mt][1], a[mt][2], a[mt][3], addr);
            }
            uint32_t b[2][4];
            #pragma unroll
            for (int np = 0; np < 2; np++) {
                uint32_t addr = bb + ((wn * 32 + np * 16 + b_n) * LDA + k0 + b_k) * 2;
                ldsm_x4(b[np][0], b[np][1], b[np][2], b[np][3], addr);
            }
            #pragma unroll
            for (int mt = 0; mt < 4; mt++)
                #pragma unroll
                for (int nt = 0; nt < 4; nt++)
                    mma16816(acc[mt][nt],
                             a[mt][0], a[mt][1], a[mt][2], a[mt][3],
                             b[nt >> 1][(nt & 1) * 2], b[nt >> 1][(nt & 1) * 2 + 1]);
        }

        if (has_next) {
            const int nb = buf ^ 1;
            *(float4*)&As[nb][row0 * LDA + q0 * 8] = pA0;
            *(float4*)&As[nb][row1 * LDA + q1 * 8] = pA1;
            *(float4*)&Bs[nb][row0 * LDA + q0 * 8] = pB0;
            *(float4*)&Bs[nb][row1 * LDA + q1 * 8] = pB1;
            __syncthreads();
            buf = nb;
        }
    }

    const int g  = lane >> 2;
    const int tg = lane & 3;
    if (z == 0) {
        #pragma unroll
        for (int mt = 0; mt < 4; mt++) {
            const int row = m0 + wm * 64 + mt * 16 + g;
            float* Crow0 = g_q + (size_t)row * DM;
            float* Crow1 = g_q + (size_t)(row + 8) * DM;
            #pragma unroll
            for (int nt = 0; nt < 4; nt++) {
                const int col = n0 + wn * 32 + nt * 8 + tg * 2;
                const float bx = __ldg(&bias[col]);
                const float by = __ldg(&bias[col + 1]);
                *(float2*)&Crow0[col] = make_float2(acc[mt][nt][0] + bx, acc[mt][nt][1] + by);
                *(float2*)&Crow1[col] = make_float2(acc[mt][nt][2] + bx, acc[mt][nt][3] + by);
            }
        }
    } else {
        __half* Ch = (z == 1) ? g_kh : g_vh;
        #pragma unroll
        for (int mt = 0; mt < 4; mt++) {
            const int row = m0 + wm * 64 + mt * 16 + g;
            __half* Crow0 = Ch + (size_t)row * DM;
            __half* Crow1 = Ch + (size_t)(row + 8) * DM;
            #pragma unroll
            for (int nt = 0; nt < 4; nt++) {
                const int col = n0 + wn * 32 + nt * 8 + tg * 2;
                const float bx = __ldg(&bias[col]);
                const float by = __ldg(&bias[col + 1]);
                __half2 h0 = __floats2half2_rn(acc[mt][nt][0] + bx, acc[mt][nt][1] + by);
                __half2 h1 = __floats2half2_rn(acc[mt][nt][2] + bx, acc[mt][nt][3] + by);
                *(uint32_t*)&Crow0[col] = *(uint32_t*)&h0;
                *(uint32_t*)&Crow1[col] = *(uint32_t*)&h1;
            }
        }
    }
}

// ---------------------------------------------------------------------------
// Windowed attention, v6: fp16 K/V loaded directly (no cvt), smem k/v stride
// 72 halves (16B-aligned uint4 stores), direct register pooling (no o_sm).
// ---------------------------------------------------------------------------
#define KVS 72   // k/v smem row stride in halves

__global__ __launch_bounds__(256, 3) void attn_kernel()
{
    const int tile = blockIdx.x;
    const int h    = blockIdx.y;
    const int b    = blockIdx.z;
    const int s0   = tile * 64;
    const int colbase = h * HD;

    extern __shared__ __align__(16) char smraw[];
    float*  q_sm = (float*)smraw;                       // 64 x 68 f32 (then weights)
    __half* k_sm = (__half*)(smraw + 17408);            // 128 x 72 f16
    __half* v_sm = (__half*)(smraw + 17408 + 18432);    // 128 x 72 f16
    float*  p_sm = (float*)(smraw + 17408);             // reuse k region for pool

    const int tid = threadIdx.x;

    // Load Q tile (fp32)
    for (int i = tid; i < 64 * 16; i += 256) {
        int row = i >> 4;
        int c4  = (i & 15) << 2;
        float4 v = *(const float4*)&g_q[((b * S_LEN) + s0 + row) * DM + colbase + c4];
        *(float4*)&q_sm[row * 68 + c4] = v;
    }
    // Load K/V window directly as fp16 (uint4 = 8 halves per op)
    for (int i = tid; i < 128 * 8; i += 256) {
        int row  = i >> 3;
        int c8   = (i & 7) << 3;
        int srow = s0 - 32 + row;
        uint4 ku = make_uint4(0u, 0u, 0u, 0u);
        uint4 vu = make_uint4(0u, 0u, 0u, 0u);
        if (srow >= 0 && srow < S_LEN) {
            size_t off = ((size_t)(b * S_LEN) + srow) * DM + colbase + c8;
            ku = *(const uint4*)&g_kh[off];
            vu = *(const uint4*)&g_vh[off];
        }
        *(uint4*)&k_sm[row * KVS + c8] = ku;
        *(uint4*)&v_sm[row * KVS + c8] = vu;
    }
    __syncthreads();

    const int grp = tid >> 4;       // 0..15 query-quad group
    const int sub = tid & 15;       // lane within group
    const int qA  = grp * 4;

    int ro[5];
    #pragma unroll
    for (int j = 0; j < 5; j++) {
        int rsm = qA + sub + 16 * j;
        if (rsm > 127) rsm = 127;
        ro[j] = rsm * KVS;
    }

    float sc[5][4];
    #pragma unroll
    for (int j = 0; j < 5; j++)
        #pragma unroll
        for (int c = 0; c < 4; c++) sc[j][c] = 0.f;

    #pragma unroll
    for (int dc = 0; dc < 16; dc++) {
        float4 qv[4];
        #pragma unroll
        for (int c = 0; c < 4; c++)
            qv[c] = *(const float4*)&q_sm[(qA + c) * 68 + dc * 4];
        #pragma unroll
        for (int j = 0; j < 5; j++) {
            uint2 kraw = *(const uint2*)&k_sm[ro[j] + dc * 4];
            float2 k01 = __half22float2(*(__half2*)&kraw.x);
            float2 k23 = __half22float2(*(__half2*)&kraw.y);
            #pragma unroll
            for (int c = 0; c < 4; c++) {
                sc[j][c] = fmaf(qv[c].x, k01.x, sc[j][c]);
                sc[j][c] = fmaf(qv[c].y, k01.y, sc[j][c]);
                sc[j][c] = fmaf(qv[c].z, k23.x, sc[j][c]);
                sc[j][c] = fmaf(qv[c].w, k23.y, sc[j][c]);
            }
        }
    }

    #pragma unroll
    for (int j = 0; j < 5; j++) {
        int rsm = qA + sub + 16 * j;
        int gk  = s0 + rsm - 32;
        bool rowok = (rsm <= 127) && (gk >= 0) && (gk < S_LEN);
        #pragma unroll
        for (int c = 0; c < 4; c++) {
            int w = sub + 16 * j - c;
            bool ok = rowok && (w >= 0) && (w <= 64);
            sc[j][c] = ok ? sc[j][c] * 0.125f : -1e9f;
        }
    }

    float mx[4], lsum[4];
    #pragma unroll
    for (int c = 0; c < 4; c++) {
        float m = -1e30f;
        #pragma unroll
        for (int j = 0; j < 5; j++) m = fmaxf(m, sc[j][c]);
        #pragma unroll
        for (int o = 1; o <= 8; o <<= 1)
            m = fmaxf(m, __shfl_xor_sync(0xffffffffu, m, o, 16));
        mx[c] = m;
    }
    #pragma unroll
    for (int c = 0; c < 4; c++) {
        float l = 0.f;
        #pragma unroll
        for (int j = 0; j < 5; j++) { sc[j][c] = __expf(sc[j][c] - mx[c]); l += sc[j][c]; }
        #pragma unroll
        for (int o = 1; o <= 8; o <<= 1)
            l += __shfl_xor_sync(0xffffffffu, l, o, 16);
        lsum[c] = 1.0f / l;
    }

    // weights -> q_sm rows (group-private, slot = sub+16j)
    #pragma unroll
    for (int j = 0; j < 5; j++) {
        int slot = sub + 16 * j;
        if (slot < 68) {
            #pragma unroll
            for (int c = 0; c < 4; c++)
                q_sm[(qA + c) * 68 + slot] = sc[j][c] * lsum[c];
        }
    }
    __syncwarp();

    // ---- AV: lane owns dims sub*4..+3 for the group's 4 queries ----
    const int d0 = sub * 4;
    float4 acc[4];
    #pragma unroll
    for (int c = 0; c < 4; c++) acc[c] = make_float4(0.f, 0.f, 0.f, 0.f);

    #pragma unroll
    for (int tb = 0; tb < 17; tb++) {
        float4 wv[4];
        #pragma unroll
        for (int c = 0; c < 4; c++)
            wv[c] = *(const float4*)&q_sm[(qA + c) * 68 + tb * 4];
        #pragma unroll
        for (int s = 0; s < 4; s++) {
            int t = tb * 4 + s;
            uint2 vraw = *(const uint2*)&v_sm[(qA + t) * KVS + d0];
            float2 v01 = __half22float2(*(__half2*)&vraw.x);
            float2 v23 = __half22float2(*(__half2*)&vraw.y);
            float w0 = (s == 0) ? wv[0].x : (s == 1) ? wv[0].y : (s == 2) ? wv[0].z : wv[0].w;
            float w1 = (s == 0) ? wv[1].x : (s == 1) ? wv[1].y : (s == 2) ? wv[1].z : wv[1].w;
            float w2 = (s == 0) ? wv[2].x : (s == 1) ? wv[2].y : (s == 2) ? wv[2].z : wv[2].w;
            float w3 = (s == 0) ? wv[3].x : (s == 1) ? wv[3].y : (s == 2) ? wv[3].z : wv[3].w;
            acc[0].x = fmaf(w0, v01.x, acc[0].x); acc[0].y = fmaf(w0, v01.y, acc[0].y);
            acc[0].z = fmaf(w0, v23.x, acc[0].z); acc[0].w = fmaf(w0, v23.y, acc[0].w);
            acc[1].x = fmaf(w1, v01.x, acc[1].x); acc[1].y = fmaf(w1, v01.y, acc[1].y);
            acc[1].z = fmaf(w1, v23.x, acc[1].z); acc[1].w = fmaf(w1, v23.y, acc[1].w);
            acc[2].x = fmaf(w2, v01.x, acc[2].x); acc[2].y = fmaf(w2, v01.y, acc[2].y);
            acc[2].z = fmaf(w2, v23.x, acc[2].z); acc[2].w = fmaf(w2, v23.y, acc[2].w);
            acc[3].x = fmaf(w3, v01.x, acc[3].x); acc[3].y = fmaf(w3, v01.y, acc[3].y);
            acc[3].z = fmaf(w3, v23.x, acc[3].z); acc[3].w = fmaf(w3, v23.y, acc[3].w);
        }
    }

    // ---- direct pooling: group partial over its 4 queries, dims d0..d0+3 ----
    float4 ps;
    ps.x = acc[0].x + acc[1].x + acc[2].x + acc[3].x;
    ps.y = acc[0].y + acc[1].y + acc[2].y + acc[3].y;
    ps.z = acc[0].z + acc[1].z + acc[2].z + acc[3].z;
    ps.w = acc[0].w + acc[1].w + acc[2].w + acc[3].w;

    __syncthreads();     // all score (k) reads done before reusing k region
    *(float4*)&p_sm[grp * 64 + d0] = ps;
    __syncthreads();

    if (tid < 64) {
        float tot = 0.f;
        #pragma unroll
        for (int gpart = 0; gpart < 16; gpart++)
            tot += p_sm[gpart * 64 + tid];
        g_part[((b * NTILE) + tile) * DM + h * HD + tid] = tot;
    }
}

// ---------------------------------------------------------------------------
// Final FC: grid (DM/64, BATCH), 256 thr: 64 outputs x 4-way K-split.
// ---------------------------------------------------------------------------
__global__ __launch_bounds__(256) void fc_kernel(
    const float* __restrict__ Wfc, const float* __restrict__ bfc,
    float* __restrict__ out)
{
    __shared__ float pooled[DM];
    __shared__ float red[4][64];
    const int b   = blockIdx.y;
    const int tid = threadIdx.x;

    for (int i = tid; i < DM; i += 256) {
        float s = 0.f;
        #pragma unroll
        for (int t = 0; t < NTILE; t++)
            s += g_part[(b * NTILE + t) * DM + i];
        pooled[i] = s * (1.0f / (float)S_LEN);
    }
    __syncthreads();

    const int split = tid >> 6;           // 0..3
    const int olocal = tid & 63;
    const int o = blockIdx.x * 64 + olocal;
    float acc = 0.f;
    const int i0 = split * 192;
    #pragma unroll 4
    for (int i = i0; i < i0 + 192; i++)
        acc = fmaf(pooled[i], Wfc[i * DM + o], acc);
    red[split][olocal] = acc;
    __syncthreads();
    if (tid < 64) {
        float r = red[0][tid] + red[1][tid] + red[2][tid] + red[3][tid] + bfc[blockIdx.x * 64 + tid];
        out[b * DM + blockIdx.x * 64 + tid] = fmaxf(r, 0.f);
    }
}

// ---------------------------------------------------------------------------
extern "C" void kernel_launch(void* const* d_in, const int* in_sizes, int n_in,
                              void* d_out, int out_size)
{
    const float* x   = (const float*)d_in[0];
    const float* Wq  = (const float*)d_in[1];
    const float* bq  = (const float*)d_in[2];
    const float* Wk  = (const float*)d_in[3];
    const float* bk  = (const float*)d_in[4];
    const float* Wv  = (const float*)d_in[5];
    const float* bv  = (const float*)d_in[6];
    const float* Wfc = (const float*)d_in[7];
    const float* bfc = (const float*)d_in[8];
    float* out = (float*)d_out;

    conv_x<<<(MROWS * DM) / 256, 256>>>(x);
    conv_w<<<dim3(DM / 32, DM / 32, 3), dim3(32, 8)>>>(Wq, Wk, Wv);

    tc_gemm<<<dim3(DM / 128, MROWS / 128, 3), 256>>>(bq, bk, bv);

    // attn smem: 17408 (q f32) + 2*18432 (k/v f16 stride 72) = 54272 B
    const int attn_smem = 17408 + 2 * 18432;
    cudaFuncSetAttribute(attn_kernel,
                         cudaFuncAttributeMaxDynamicSharedMemorySize, attn_smem);
    attn_kernel<<<dim3(NTILE, NH, BATCH), 256, attn_smem>>>();

    fc_kernel<<<dim3(DM / 64, BATCH), 256>>>(Wfc, bfc, out);
}